// round 13
// baseline (speedup 1.0000x reference)
#include <cuda_runtime.h>
#include <cuda_fp16.h>
#include <cuda_bf16.h>
#include <math.h>

#define NT_   32768
#define B_    16
#define N_    2048
#define INCH_ 128
#define H_    4
#define C_    64
#define HC_   256
#define E_    524288
#define FC0_  1024
#define FC1_  512
#define OMIC_ 128
#define OUT_  2

// ---------------- scratch (static device globals) --------------------------
__device__ __align__(16) float g_xw[NT_ * HC_];
__device__ __align__(16) __half g_xwh[NT_ * HC_];
__device__ __align__(16) float g_h [NT_ * HC_];
__device__ __align__(16) float g_asrc[NT_ * 4];
__device__ __align__(16) float g_adst[NT_ * 4];
__device__ int   g_deg[NT_];
__device__ int   g_cur[NT_];
__device__ int   g_row[NT_ + 1];
__device__ int   g_blk[128];
__device__ int   g_csr[E_];
__device__ __align__(16) float g_feat[B_ * 3 * N_];
__device__ __align__(16) float g_part[12 * B_ * FC0_];
__device__ __align__(16) float g_e1[B_ * FC1_];
__device__ int   g_i64;

__device__ __forceinline__ float elu1(float x)  { return x > 0.f ? x : (expf(x) - 1.f); }
__device__ __forceinline__ float lrelu(float x) { return x > 0.f ? x : 0.2f * x; }

__device__ __forceinline__ int ld_idx(const void* ei, int i) {
    if (g_i64) return (int)((const long long*)ei)[i];
    return ((const int*)ei)[i];
}

// ---------------- zero + detect + x0 (fused) ---------------------------------
__global__ void k_zero(const void* ei, const float* __restrict__ x) {
    int tid = blockIdx.x * blockDim.x + threadIdx.x;
    if (tid < NT_) { g_deg[tid] = 0; g_cur[tid] = 0; }
    if (blockIdx.x == 0 && threadIdx.x < 32) {
        const long long* p64 = (const long long*)ei;
        long long v = p64[threadIdx.x];
        unsigned bad = __ballot_sync(0xffffffffu, v < 0 || v >= NT_);
        if (threadIdx.x == 0) g_i64 = (bad == 0);
    }
    int n = tid >> 5;
    int lane = threadIdx.x & 31;
    if (n < NT_) {
        float4 v = *(const float4*)(x + (size_t)n * INCH_ + lane * 4);
        float s = v.x + v.y + v.z + v.w;
#pragma unroll
        for (int off = 16; off >= 1; off >>= 1)
            s += __shfl_xor_sync(0xffffffffu, s, off);
        if (lane == 0)
            g_feat[(n >> 11) * (3 * N_) + (n & 2047)] = s * (1.f / 128.f);
    }
}

__global__ void k_deg(const void* __restrict__ ei) {
    int e = blockIdx.x * blockDim.x + threadIdx.x;
    if (e < E_) atomicAdd(&g_deg[ld_idx(ei, E_ + e) & (NT_ - 1)], 1);
}

__global__ void k_scan1() {
    __shared__ int wt[8];
    int t = threadIdx.x;
    int i = blockIdx.x * 256 + t;
    int v = g_deg[i];
    int lane = t & 31, w = t >> 5;
    int inc = v;
#pragma unroll
    for (int off = 1; off < 32; off <<= 1) {
        int u = __shfl_up_sync(0xffffffffu, inc, off);
        if (lane >= off) inc += u;
    }
    if (lane == 31) wt[w] = inc;
    __syncthreads();
    if (t == 0) {
        int run = 0;
#pragma unroll
        for (int k = 0; k < 8; k++) { int x = wt[k]; wt[k] = run; run += x; }
        g_blk[blockIdx.x] = run;
    }
    __syncthreads();
    g_row[i] = inc - v + wt[w];
}

__global__ void k_scan3b() {
    __shared__ int part[4];
    int t = threadIdx.x;
    int v = (t < 128 && t < blockIdx.x) ? g_blk[t] : 0;
    if (t < 128) {
        int u = v;
#pragma unroll
        for (int off = 16; off >= 1; off >>= 1)
            u += __shfl_xor_sync(0xffffffffu, u, off);
        if ((t & 31) == 0) part[t >> 5] = u;
    }
    __syncthreads();
    int pre = part[0] + part[1] + part[2] + part[3];
    g_row[blockIdx.x * 256 + t] += pre;
    if (blockIdx.x == 127 && t == 255) g_row[NT_] = pre + g_blk[127];
}

__global__ void k_scatter(const void* __restrict__ ei) {
    int e = blockIdx.x * blockDim.x + threadIdx.x;
    if (e < E_) {
        int d = ld_idx(ei, E_ + e) & (NT_ - 1);
        int s = ld_idx(ei, e) & (NT_ - 1);
        int pos = g_row[d] + atomicAdd(&g_cur[d], 1);
        g_csr[pos] = s;
    }
}

__global__ void k_sortseg() {
    int n = blockIdx.x * blockDim.x + threadIdx.x;
    if (n >= NT_) return;
    int r0 = g_row[n], r1 = g_row[n + 1];
    int len = r1 - r0;
    if (len <= 1) return;
    if (len <= 96) {
        int buf[96];
        for (int i = 0; i < len; i++) buf[i] = g_csr[r0 + i];
        for (int i = 1; i < len; i++) {
            int v = buf[i]; int j = i - 1;
            while (j >= 0 && buf[j] > v) { buf[j + 1] = buf[j]; j--; }
            buf[j + 1] = v;
        }
        for (int i = 0; i < len; i++) g_csr[r0 + i] = buf[i];
    } else {
        for (int i = r0 + 1; i < r1; i++) {
            int v = g_csr[i]; int j = i - 1;
            while (j >= r0 && g_csr[j] > v) { g_csr[j + 1] = g_csr[j]; j--; }
            g_csr[j + 1] = v;
        }
    }
}

// ---------------- bf16 3-pass tensor GEMM + fused attention dots -------------
__device__ __forceinline__ void mma16(float* c, const unsigned* a,
                                      unsigned b0, unsigned b1) {
    asm volatile(
        "mma.sync.aligned.m16n8k16.row.col.f32.bf16.bf16.f32 "
        "{%0,%1,%2,%3},{%4,%5,%6,%7},{%8,%9},{%0,%1,%2,%3};"
        : "+f"(c[0]), "+f"(c[1]), "+f"(c[2]), "+f"(c[3])
        : "r"(a[0]), "r"(a[1]), "r"(a[2]), "r"(a[3]), "r"(b0), "r"(b1));
}

__device__ __forceinline__ unsigned sptr(const void* p) {
    return (unsigned)__cvta_generic_to_shared(p);
}

__device__ __forceinline__ void ldsm4(unsigned* r, unsigned addr) {
    asm volatile("ldmatrix.sync.aligned.m8n8.x4.shared.b16 {%0,%1,%2,%3}, [%4];"
                 : "=r"(r[0]), "=r"(r[1]), "=r"(r[2]), "=r"(r[3]) : "r"(addr));
}

__device__ __forceinline__ void ldsm4t(unsigned* r, unsigned addr) {
    asm volatile("ldmatrix.sync.aligned.m8n8.x4.trans.shared.b16 {%0,%1,%2,%3}, [%4];"
                 : "=r"(r[0]), "=r"(r[1]), "=r"(r[2]), "=r"(r[3]) : "r"(addr));
}

__global__ __launch_bounds__(256, 2)
void k_gemm_tc(const float* __restrict__ Aext, int useH,
               const float* __restrict__ W, int K,
               const float* __restrict__ att_s, const float* __restrict__ att_d) {
    const float* A = useH ? (const float*)g_h : Aext;
    __shared__ __nv_bfloat16 AsH[128][40];
    __shared__ __nv_bfloat16 AsL[128][40];
    __shared__ __nv_bfloat16 BsH[32][136];
    __shared__ __nv_bfloat16 BsL[32][136];
    int tid = threadIdx.x;
    int lid = tid & 31, wid = tid >> 5;
    int wr = wid >> 1, wc = wid & 1;
    int lrow = lid & 7, seg = lid >> 3;

    const float* Ab = A + (size_t)blockIdx.x * 128 * K;
    const float* Wb = W + blockIdx.y * 128;

    float c[2][8][4];
#pragma unroll
    for (int mt = 0; mt < 2; mt++)
#pragma unroll
        for (int nt = 0; nt < 8; nt++)
#pragma unroll
            for (int q = 0; q < 4; q++) c[mt][nt][q] = 0.f;

    for (int k0 = 0; k0 < K; k0 += 32) {
#pragma unroll
        for (int i = 0; i < 4; i++) {
            int id = tid + 256 * i;
            int row = id >> 3, kq = id & 7;
            float4 v = *(const float4*)(Ab + (size_t)row * K + k0 + kq * 4);
            __nv_bfloat162 h01 = __floats2bfloat162_rn(v.x, v.y);
            __nv_bfloat162 h23 = __floats2bfloat162_rn(v.z, v.w);
            __nv_bfloat162 l01 = __floats2bfloat162_rn(v.x - __bfloat162float(h01.x),
                                                       v.y - __bfloat162float(h01.y));
            __nv_bfloat162 l23 = __floats2bfloat162_rn(v.z - __bfloat162float(h23.x),
                                                       v.w - __bfloat162float(h23.y));
            *(__nv_bfloat162*)&AsH[row][kq * 4]     = h01;
            *(__nv_bfloat162*)&AsH[row][kq * 4 + 2] = h23;
            *(__nv_bfloat162*)&AsL[row][kq * 4]     = l01;
            *(__nv_bfloat162*)&AsL[row][kq * 4 + 2] = l23;
        }
#pragma unroll
        for (int i = 0; i < 4; i++) {
            int id = tid + 256 * i;
            int kr = id >> 5, nq = id & 31;
            float4 v = *(const float4*)(Wb + (size_t)(k0 + kr) * HC_ + nq * 4);
            __nv_bfloat162 h01 = __floats2bfloat162_rn(v.x, v.y);
            __nv_bfloat162 h23 = __floats2bfloat162_rn(v.z, v.w);
            __nv_bfloat162 l01 = __floats2bfloat162_rn(v.x - __bfloat162float(h01.x),
                                                       v.y - __bfloat162float(h01.y));
            __nv_bfloat162 l23 = __floats2bfloat162_rn(v.z - __bfloat162float(h23.x),
                                                       v.w - __bfloat162float(h23.y));
            *(__nv_bfloat162*)&BsH[kr][nq * 4]     = h01;
            *(__nv_bfloat162*)&BsH[kr][nq * 4 + 2] = h23;
            *(__nv_bfloat162*)&BsL[kr][nq * 4]     = l01;
            *(__nv_bfloat162*)&BsL[kr][nq * 4 + 2] = l23;
        }
        __syncthreads();

#pragma unroll
        for (int ks = 0; ks < 2; ks++) {
            int kc = ks * 16;
            unsigned aH[2][4], aL[2][4];
            int ar = (seg & 1) * 8 + lrow;
            int ac = kc + (seg >> 1) * 8;
#pragma unroll
            for (int mt = 0; mt < 2; mt++) {
                int m = wr * 32 + mt * 16 + ar;
                ldsm4(aH[mt], sptr(&AsH[m][ac]));
                ldsm4(aL[mt], sptr(&AsL[m][ac]));
            }
            int br = kc + (seg & 1) * 8 + lrow;
            int bcoff = (seg >> 1) * 8;
#pragma unroll
            for (int ntp = 0; ntp < 4; ntp++) {
                int n0 = wc * 64 + ntp * 16 + bcoff;
                unsigned bH[4], bL[4];
                ldsm4t(bH, sptr(&BsH[br][n0]));
                ldsm4t(bL, sptr(&BsL[br][n0]));
#pragma unroll
                for (int half = 0; half < 2; half++) {
                    int nt = 2 * ntp + half;
                    unsigned b0H = bH[2 * half], b1H = bH[2 * half + 1];
                    unsigned b0L = bL[2 * half], b1L = bL[2 * half + 1];
#pragma unroll
                    for (int mt = 0; mt < 2; mt++) {
                        mma16(c[mt][nt], aH[mt], b0H, b1H);
                        mma16(c[mt][nt], aL[mt], b0H, b1H);
                        mma16(c[mt][nt], aH[mt], b0L, b1L);
                    }
                }
            }
        }
        __syncthreads();
    }

    int g4 = lid >> 2, t4 = lid & 3;

#pragma unroll
    for (int mt = 0; mt < 2; mt++) {
#pragma unroll
        for (int nt = 0; nt < 8; nt++) {
            int row = blockIdx.x * 128 + wr * 32 + mt * 16 + g4;
            int col = blockIdx.y * 128 + wc * 64 + nt * 8 + 2 * t4;
            float2 v0 = {c[mt][nt][0], c[mt][nt][1]};
            float2 v1 = {c[mt][nt][2], c[mt][nt][3]};
            *(float2*)(g_xw + (size_t)row * HC_ + col)       = v0;
            *(float2*)(g_xw + (size_t)(row + 8) * HC_ + col) = v1;
            *(__half2*)(g_xwh + (size_t)row * HC_ + col)       = __floats2half2_rn(v0.x, v0.y);
            *(__half2*)(g_xwh + (size_t)(row + 8) * HC_ + col) = __floats2half2_rn(v1.x, v1.y);
        }
    }

    int head = blockIdx.y * 2 + wc;
    const float* Asv = att_s + head * 64;
    const float* Adv = att_d + head * 64;
#pragma unroll
    for (int mt = 0; mt < 2; mt++) {
        float s0 = 0.f, s1 = 0.f, d0 = 0.f, d1 = 0.f;
#pragma unroll
        for (int nt = 0; nt < 8; nt++) {
            int cb = nt * 8 + 2 * t4;
            float a0 = Asv[cb], a1 = Asv[cb + 1];
            float b0 = Adv[cb], b1 = Adv[cb + 1];
            s0 += c[mt][nt][0] * a0 + c[mt][nt][1] * a1;
            s1 += c[mt][nt][2] * a0 + c[mt][nt][3] * a1;
            d0 += c[mt][nt][0] * b0 + c[mt][nt][1] * b1;
            d1 += c[mt][nt][2] * b0 + c[mt][nt][3] * b1;
        }
#pragma unroll
        for (int off = 1; off <= 2; off <<= 1) {
            s0 += __shfl_xor_sync(0xffffffffu, s0, off);
            s1 += __shfl_xor_sync(0xffffffffu, s1, off);
            d0 += __shfl_xor_sync(0xffffffffu, d0, off);
            d1 += __shfl_xor_sync(0xffffffffu, d1, off);
        }
        if (t4 == 0) {
            int r = blockIdx.x * 128 + wr * 32 + mt * 16 + g4;
            g_asrc[r * 4 + head]       = s0;
            g_adst[r * 4 + head]       = d0;
            g_asrc[(r + 8) * 4 + head] = s1;
            g_adst[(r + 8) * 4 + head] = d1;
        }
    }
}

// ---------------- GAT aggregation (warp per node, fp16 gather, unroll 2) ------
__global__ void k_agg(const float* __restrict__ bias,
                      const float* __restrict__ poolw,
                      const float* __restrict__ poolb,
                      int writeH, int seg) {
    int n = (blockIdx.x * blockDim.x + threadIdx.x) >> 5;
    int lane = threadIdx.x & 31;
    if (n >= NT_) return;
    int h = lane >> 3;

    float4 d4 = *(const float4*)(g_adst + n * 4);
    float4 s4 = *(const float4*)(g_asrc + n * 4);
    float adh = (h == 0) ? d4.x : (h == 1) ? d4.y : (h == 2) ? d4.z : d4.w;
    float ash = (h == 0) ? s4.x : (h == 1) ? s4.y : (h == 2) ? s4.z : s4.w;

    int r0 = g_row[n], r1 = g_row[n + 1];

    float wself = __expf(lrelu(ash + adh));
    float den = wself;
    const float4* xp = (const float4*)(g_xw + (size_t)n * HC_ + lane * 8);
    float4 q0 = xp[0], q1 = xp[1];
    float4 acc0 = {wself*q0.x, wself*q0.y, wself*q0.z, wself*q0.w};
    float4 acc1 = {wself*q1.x, wself*q1.y, wself*q1.z, wself*q1.w};

    int e = r0;
    for (; e + 2 <= r1; e += 2) {
        int sa = g_csr[e], sb = g_csr[e + 1];
        float aa = g_asrc[sa * 4 + h];
        float ab = g_asrc[sb * 4 + h];
        uint4 qa = *(const uint4*)(g_xwh + (size_t)sa * HC_ + lane * 8);
        uint4 qb = *(const uint4*)(g_xwh + (size_t)sb * HC_ + lane * 8);
        float wa = __expf(lrelu(aa + adh));
        float wb = __expf(lrelu(ab + adh));
        den += wa + wb;
        float2 a0 = __half22float2(*(__half2*)&qa.x);
        float2 a1 = __half22float2(*(__half2*)&qa.y);
        float2 a2 = __half22float2(*(__half2*)&qa.z);
        float2 a3 = __half22float2(*(__half2*)&qa.w);
        float2 b0 = __half22float2(*(__half2*)&qb.x);
        float2 b1 = __half22float2(*(__half2*)&qb.y);
        float2 b2 = __half22float2(*(__half2*)&qb.z);
        float2 b3 = __half22float2(*(__half2*)&qb.w);
        acc0.x += wa*a0.x + wb*b0.x; acc0.y += wa*a0.y + wb*b0.y;
        acc0.z += wa*a1.x + wb*b1.x; acc0.w += wa*a1.y + wb*b1.y;
        acc1.x += wa*a2.x + wb*b2.x; acc1.y += wa*a2.y + wb*b2.y;
        acc1.z += wa*a3.x + wb*b3.x; acc1.w += wa*a3.y + wb*b3.y;
    }
    for (; e < r1; e++) {
        int s = g_csr[e];
        float as = g_asrc[s * 4 + h];
        float wgt = __expf(lrelu(as + adh));
        den += wgt;
        uint4 q = *(const uint4*)(g_xwh + (size_t)s * HC_ + lane * 8);
        float2 f0 = __half22float2(*(__half2*)&q.x);
        float2 f1 = __half22float2(*(__half2*)&q.y);
        float2 f2 = __half22float2(*(__half2*)&q.z);
        float2 f3 = __half22float2(*(__half2*)&q.w);
        acc0.x += wgt * f0.x; acc0.y += wgt * f0.y;
        acc0.z += wgt * f1.x; acc0.w += wgt * f1.y;
        acc1.x += wgt * f2.x; acc1.y += wgt * f2.y;
        acc1.z += wgt * f3.x; acc1.w += wgt * f3.y;
    }
    float rden = 1.f / (den + 1e-16f);
    acc0.x *= rden; acc0.y *= rden; acc0.z *= rden; acc0.w *= rden;
    acc1.x *= rden; acc1.y *= rden; acc1.z *= rden; acc1.w *= rden;

    const float* bp = bias + lane * 8;
    float v[8];
    v[0] = elu1(acc0.x + bp[0]); v[1] = elu1(acc0.y + bp[1]);
    v[2] = elu1(acc0.z + bp[2]); v[3] = elu1(acc0.w + bp[3]);
    v[4] = elu1(acc1.x + bp[4]); v[5] = elu1(acc1.y + bp[5]);
    v[6] = elu1(acc1.z + bp[6]); v[7] = elu1(acc1.w + bp[7]);

    if (writeH) {
        float4 o0 = {v[0], v[1], v[2], v[3]};
        float4 o1 = {v[4], v[5], v[6], v[7]};
        *(float4*)(g_h + (size_t)n * HC_ + lane * 8)     = o0;
        *(float4*)(g_h + (size_t)n * HC_ + lane * 8 + 4) = o1;
    }

    const float* pw = poolw + lane * 8;
    float p = v[0]*pw[0] + v[1]*pw[1] + v[2]*pw[2] + v[3]*pw[3]
            + v[4]*pw[4] + v[5]*pw[5] + v[6]*pw[6] + v[7]*pw[7];
#pragma unroll
    for (int off = 16; off >= 1; off >>= 1)
        p += __shfl_xor_sync(0xffffffffu, p, off);
    if (lane == 0)
        g_feat[(n >> 11) * (3 * N_) + seg * N_ + (n & 2047)] = p + poolb[0];
}

// ---------------- LayerNorm in place (48 rows) --------------------------------
__global__ void k_ln(const float* __restrict__ w, const float* __restrict__ b) {
    __shared__ float red[8];
    __shared__ float tot;
    int row = blockIdx.x;
    float* p = g_feat + (row / 3) * (3 * N_) + (row % 3) * N_;
    int t = threadIdx.x;
    float v[8];
    float s = 0.f;
#pragma unroll
    for (int i = 0; i < 8; i++) { v[i] = p[t + 256 * i]; s += v[i]; }
#pragma unroll
    for (int off = 16; off >= 1; off >>= 1) s += __shfl_xor_sync(0xffffffffu, s, off);
    if ((t & 31) == 0) red[t >> 5] = s;
    __syncthreads();
    if (t == 0) { float z = 0.f; for (int i = 0; i < 8; i++) z += red[i]; tot = z; }
    __syncthreads();
    float mu = tot * (1.f / 2048.f);
    float q = 0.f;
#pragma unroll
    for (int i = 0; i < 8; i++) { float d = v[i] - mu; q += d * d; }
#pragma unroll
    for (int off = 16; off >= 1; off >>= 1) q += __shfl_xor_sync(0xffffffffu, q, off);
    __syncthreads();
    if ((t & 31) == 0) red[t >> 5] = q;
    __syncthreads();
    if (t == 0) { float z = 0.f; for (int i = 0; i < 8; i++) z += red[i]; tot = z; }
    __syncthreads();
    float r = rsqrtf(tot * (1.f / 2048.f) + 1e-5f);
#pragma unroll
    for (int i = 0; i < 8; i++) {
        int idx = t + 256 * i;
        p[idx] = (v[i] - mu) * r * w[idx] + b[idx];
    }
}

// ---------------- fc0 partial GEMM (12 k-splits) ------------------------------
__global__ void k_fc0(const float* __restrict__ W) {
    __shared__ float sa[16][128];
    int tid = threadIdx.x;
    int j = blockIdx.x * 128 + tid;
    int k0 = blockIdx.y * 512;
    float acc[16];
#pragma unroll
    for (int bi = 0; bi < 16; bi++) acc[bi] = 0.f;
    for (int kt = k0; kt < k0 + 512; kt += 128) {
#pragma unroll
        for (int i = 0; i < 16; i++) sa[i][tid] = g_feat[i * (3 * N_) + kt + tid];
        __syncthreads();
#pragma unroll 8
        for (int kk = 0; kk < 128; kk++) {
            float wv = W[(size_t)(kt + kk) * FC0_ + j];
#pragma unroll
            for (int bi = 0; bi < 16; bi++) acc[bi] += sa[bi][kk] * wv;
        }
        __syncthreads();
    }
#pragma unroll
    for (int bi = 0; bi < 16; bi++)
        g_part[((size_t)blockIdx.y * 16 + bi) * FC0_ + j] = acc[bi];
}

// ---------------- fc1: e0 (rebuilt in smem) @ W1 -> g_e1, weights read once ---
__global__ __launch_bounds__(128)
void k_fc1(const float* __restrict__ e0b,
           const float* __restrict__ e1w, const float* __restrict__ e1b) {
    __shared__ float se0[8][FC0_];        // 32 KB
    int tid = threadIdx.x;                // 128
    int j = blockIdx.x * 128 + tid;       // 4 blocks cover FC1=512
    float acc[16];
#pragma unroll
    for (int bi = 0; bi < 16; bi++) acc[bi] = 0.f;

    for (int chunk = 0; chunk < 2; chunk++) {
        for (int idx = tid; idx < 8 * FC0_; idx += 128) {
            int b = chunk * 8 + (idx >> 10);
            int j0 = idx & (FC0_ - 1);
            float s = 0.f;
#pragma unroll
            for (int p = 0; p < 12; p++)
                s += g_part[((size_t)p * 16 + b) * FC0_ + j0];
            se0[idx >> 10][j0] = elu1(s + e0b[j0]);
        }
        __syncthreads();
#pragma unroll 4
        for (int k = 0; k < FC0_; k++) {
            float wv = e1w[(size_t)k * FC1_ + j];
#pragma unroll
            for (int bi = 0; bi < 8; bi++)
                acc[chunk * 8 + bi] += se0[bi][k] * wv;
        }
        __syncthreads();
    }
#pragma unroll
    for (int bi = 0; bi < 16; bi++)
        g_e1[bi * FC1_ + j] = elu1(acc[bi] + e1b[j]);
}

// ---------------- tail: e2 + final linear (1 block) ---------------------------
__global__ __launch_bounds__(1024)
void k_tail2(const float* __restrict__ e2w, const float* __restrict__ e2b,
             const float* __restrict__ lw,  const float* __restrict__ lb,
             float* __restrict__ out, int out_n) {
    __shared__ float se1[B_ * FC1_];      // 32 KB
    __shared__ float se2[B_ * OMIC_];     // 8 KB
    int t = threadIdx.x;                  // 1024
    for (int i = t; i < B_ * FC1_; i += 1024) se1[i] = g_e1[i];
    __syncthreads();
#pragma unroll
    for (int o = t; o < B_ * OMIC_; o += 1024) {
        int b = o >> 7, j = o & (OMIC_ - 1);
        float s = 0.f;
        for (int k = 0; k < FC1_; k++)
            s += se1[b * FC1_ + k] * e2w[(size_t)k * OMIC_ + j];
        se2[o] = elu1(s + e2b[j]);
    }
    __syncthreads();
    if (t < 32 && t < out_n) {
        int bi = t >> 1, o = t & 1;
        float a = 0.f;
        for (int k = 0; k < OMIC_; k++) a += se2[bi * OMIC_ + k] * lw[k * 2 + o];
        out[t] = a + lb[o];
    }
}

// ---------------- driver --------------------------------------------------------
extern "C" void kernel_launch(void* const* d_in, const int* in_sizes, int n_in,
                              void* d_out, int out_size) {
    const float* x   = (const float*)d_in[0];
    const void*  ei  = d_in[1];
    const float* w1  = (const float*)d_in[2];
    const float* as1 = (const float*)d_in[3];
    const float* ad1 = (const float*)d_in[4];
    const float* b1  = (const float*)d_in[5];
    const float* p1w = (const float*)d_in[6];
    const float* p1b = (const float*)d_in[7];
    const float* w2  = (const float*)d_in[8];
    const float* as2 = (const float*)d_in[9];
    const float* ad2 = (const float*)d_in[10];
    const float* b2  = (const float*)d_in[11];
    const float* p2w = (const float*)d_in[12];
    const float* p2b = (const float*)d_in[13];
    const float* lnw = (const float*)d_in[14];
    const float* lnb = (const float*)d_in[15];
    const float* e0w = (const float*)d_in[16];
    const float* e0b = (const float*)d_in[17];
    const float* e1w = (const float*)d_in[18];
    const float* e1b = (const float*)d_in[19];
    const float* e2w = (const float*)d_in[20];
    const float* e2b = (const float*)d_in[21];
    const float* lw  = (const float*)d_in[22];
    const float* lb  = (const float*)d_in[23];
    float* out = (float*)d_out;

    k_zero<<<4096, 256>>>(ei, x);                                      // 1
    k_deg<<<E_ / 256, 256>>>(ei);                                      // 2
    k_scan1<<<128, 256>>>();                                           // 3
    k_gemm_tc<<<dim3(NT_ / 128, 2), 256>>>(x, 0, w1, INCH_, as1, ad1); // 4 <- profiled
    k_scan3b<<<128, 256>>>();                                          // 5
    k_scatter<<<E_ / 256, 256>>>(ei);                                  // 6
    k_sortseg<<<NT_ / 256, 256>>>();                                   // 7
    k_agg<<<NT_ / 8, 256>>>(b1, p1w, p1b, 1, 1);                       // 8
    k_gemm_tc<<<dim3(NT_ / 128, 2), 256>>>(nullptr, 1, w2, HC_, as2, ad2); // 9
    k_agg<<<NT_ / 8, 256>>>(b2, p2w, p2b, 0, 2);                       // 10
    k_ln<<<48, 256>>>(lnw, lnb);                                       // 11
    k_fc0<<<dim3(FC0_ / 128, 12), 128>>>(e0w);                         // 12
    k_fc1<<<4, 128>>>(e0b, e1w, e1b);                                  // 13
    k_tail2<<<1, 1024>>>(e2w, e2b, lw, lb, out, out_size);             // 14
}

// round 14
// speedup vs baseline: 1.5498x; 1.5498x over previous
#include <cuda_runtime.h>
#include <cuda_fp16.h>
#include <cuda_bf16.h>
#include <math.h>

#define NT_   32768
#define B_    16
#define N_    2048
#define INCH_ 128
#define H_    4
#define C_    64
#define HC_   256
#define E_    524288
#define FC0_  1024
#define FC1_  512
#define OMIC_ 128
#define OUT_  2

// ---------------- scratch (static device globals) --------------------------
__device__ __align__(16) __half g_xwh[NT_ * HC_];   // fp16 transform output
__device__ __align__(16) float g_h [NT_ * HC_];
__device__ __align__(16) float g_asrc[NT_ * 4];
__device__ __align__(16) float g_adst[NT_ * 4];
__device__ int   g_deg[NT_];
__device__ int   g_cur[NT_];
__device__ int   g_row[NT_ + 1];
__device__ int   g_blk[128];
__device__ int   g_csr[E_];
__device__ __align__(16) float g_feat[B_ * 3 * N_];
__device__ __align__(16) float g_part[12 * B_ * FC0_];
__device__ int   g_i64;

__device__ __forceinline__ float elu1(float x)  { return x > 0.f ? x : (expf(x) - 1.f); }
__device__ __forceinline__ float lrelu(float x) { return x > 0.f ? x : 0.2f * x; }

__device__ __forceinline__ int ld_idx(const void* ei, int i) {
    if (g_i64) return (int)((const long long*)ei)[i];
    return ((const int*)ei)[i];
}

// ---------------- zero + detect + x0 (fused) ---------------------------------
__global__ void k_zero(const void* ei, const float* __restrict__ x) {
    int tid = blockIdx.x * blockDim.x + threadIdx.x;
    if (tid < NT_) { g_deg[tid] = 0; g_cur[tid] = 0; }
    if (blockIdx.x == 0 && threadIdx.x < 32) {
        const long long* p64 = (const long long*)ei;
        long long v = p64[threadIdx.x];
        unsigned bad = __ballot_sync(0xffffffffu, v < 0 || v >= NT_);
        if (threadIdx.x == 0) g_i64 = (bad == 0);
    }
    int n = tid >> 5;
    int lane = threadIdx.x & 31;
    if (n < NT_) {
        float4 v = *(const float4*)(x + (size_t)n * INCH_ + lane * 4);
        float s = v.x + v.y + v.z + v.w;
#pragma unroll
        for (int off = 16; off >= 1; off >>= 1)
            s += __shfl_xor_sync(0xffffffffu, s, off);
        if (lane == 0)
            g_feat[(n >> 11) * (3 * N_) + (n & 2047)] = s * (1.f / 128.f);
    }
}

__global__ void k_deg(const void* __restrict__ ei) {
    int e = blockIdx.x * blockDim.x + threadIdx.x;
    if (e < E_) atomicAdd(&g_deg[ld_idx(ei, E_ + e) & (NT_ - 1)], 1);
}

__global__ void k_scan1() {
    __shared__ int wt[8];
    int t = threadIdx.x;
    int i = blockIdx.x * 256 + t;
    int v = g_deg[i];
    int lane = t & 31, w = t >> 5;
    int inc = v;
#pragma unroll
    for (int off = 1; off < 32; off <<= 1) {
        int u = __shfl_up_sync(0xffffffffu, inc, off);
        if (lane >= off) inc += u;
    }
    if (lane == 31) wt[w] = inc;
    __syncthreads();
    if (t == 0) {
        int run = 0;
#pragma unroll
        for (int k = 0; k < 8; k++) { int x = wt[k]; wt[k] = run; run += x; }
        g_blk[blockIdx.x] = run;
    }
    __syncthreads();
    g_row[i] = inc - v + wt[w];
}

__global__ void k_scan3b() {
    __shared__ int part[4];
    int t = threadIdx.x;
    int v = (t < 128 && t < blockIdx.x) ? g_blk[t] : 0;
    if (t < 128) {
        int u = v;
#pragma unroll
        for (int off = 16; off >= 1; off >>= 1)
            u += __shfl_xor_sync(0xffffffffu, u, off);
        if ((t & 31) == 0) part[t >> 5] = u;
    }
    __syncthreads();
    int pre = part[0] + part[1] + part[2] + part[3];
    g_row[blockIdx.x * 256 + t] += pre;
    if (blockIdx.x == 127 && t == 255) g_row[NT_] = pre + g_blk[127];
}

__global__ void k_scatter(const void* __restrict__ ei) {
    int e = blockIdx.x * blockDim.x + threadIdx.x;
    if (e < E_) {
        int d = ld_idx(ei, E_ + e) & (NT_ - 1);
        int s = ld_idx(ei, e) & (NT_ - 1);
        int pos = g_row[d] + atomicAdd(&g_cur[d], 1);
        g_csr[pos] = s;
    }
}

__global__ void k_sortseg() {
    int n = blockIdx.x * blockDim.x + threadIdx.x;
    if (n >= NT_) return;
    int r0 = g_row[n], r1 = g_row[n + 1];
    int len = r1 - r0;
    if (len <= 1) return;
    if (len <= 96) {
        int buf[96];
        for (int i = 0; i < len; i++) buf[i] = g_csr[r0 + i];
        for (int i = 1; i < len; i++) {
            int v = buf[i]; int j = i - 1;
            while (j >= 0 && buf[j] > v) { buf[j + 1] = buf[j]; j--; }
            buf[j + 1] = v;
        }
        for (int i = 0; i < len; i++) g_csr[r0 + i] = buf[i];
    } else {
        for (int i = r0 + 1; i < r1; i++) {
            int v = g_csr[i]; int j = i - 1;
            while (j >= r0 && g_csr[j] > v) { g_csr[j + 1] = g_csr[j]; j--; }
            g_csr[j + 1] = v;
        }
    }
}

// ---------------- bf16 3-pass tensor GEMM + fused attention dots -------------
__device__ __forceinline__ void mma16(float* c, const unsigned* a,
                                      unsigned b0, unsigned b1) {
    asm volatile(
        "mma.sync.aligned.m16n8k16.row.col.f32.bf16.bf16.f32 "
        "{%0,%1,%2,%3},{%4,%5,%6,%7},{%8,%9},{%0,%1,%2,%3};"
        : "+f"(c[0]), "+f"(c[1]), "+f"(c[2]), "+f"(c[3])
        : "r"(a[0]), "r"(a[1]), "r"(a[2]), "r"(a[3]), "r"(b0), "r"(b1));
}

__device__ __forceinline__ unsigned sptr(const void* p) {
    return (unsigned)__cvta_generic_to_shared(p);
}

__device__ __forceinline__ void ldsm4(unsigned* r, unsigned addr) {
    asm volatile("ldmatrix.sync.aligned.m8n8.x4.shared.b16 {%0,%1,%2,%3}, [%4];"
                 : "=r"(r[0]), "=r"(r[1]), "=r"(r[2]), "=r"(r[3]) : "r"(addr));
}

__device__ __forceinline__ void ldsm4t(unsigned* r, unsigned addr) {
    asm volatile("ldmatrix.sync.aligned.m8n8.x4.trans.shared.b16 {%0,%1,%2,%3}, [%4];"
                 : "=r"(r[0]), "=r"(r[1]), "=r"(r[2]), "=r"(r[3]) : "r"(addr));
}

__global__ __launch_bounds__(256, 2)
void k_gemm_tc(const float* __restrict__ Aext, int useH,
               const float* __restrict__ W, int K,
               const float* __restrict__ att_s, const float* __restrict__ att_d) {
    const float* A = useH ? (const float*)g_h : Aext;
    __shared__ __nv_bfloat16 AsH[128][40];
    __shared__ __nv_bfloat16 AsL[128][40];
    __shared__ __nv_bfloat16 BsH[32][136];
    __shared__ __nv_bfloat16 BsL[32][136];
    int tid = threadIdx.x;
    int lid = tid & 31, wid = tid >> 5;
    int wr = wid >> 1, wc = wid & 1;
    int lrow = lid & 7, seg = lid >> 3;

    const float* Ab = A + (size_t)blockIdx.x * 128 * K;
    const float* Wb = W + blockIdx.y * 128;

    float c[2][8][4];
#pragma unroll
    for (int mt = 0; mt < 2; mt++)
#pragma unroll
        for (int nt = 0; nt < 8; nt++)
#pragma unroll
            for (int q = 0; q < 4; q++) c[mt][nt][q] = 0.f;

    for (int k0 = 0; k0 < K; k0 += 32) {
#pragma unroll
        for (int i = 0; i < 4; i++) {
            int id = tid + 256 * i;
            int row = id >> 3, kq = id & 7;
            float4 v = *(const float4*)(Ab + (size_t)row * K + k0 + kq * 4);
            __nv_bfloat162 h01 = __floats2bfloat162_rn(v.x, v.y);
            __nv_bfloat162 h23 = __floats2bfloat162_rn(v.z, v.w);
            __nv_bfloat162 l01 = __floats2bfloat162_rn(v.x - __bfloat162float(h01.x),
                                                       v.y - __bfloat162float(h01.y));
            __nv_bfloat162 l23 = __floats2bfloat162_rn(v.z - __bfloat162float(h23.x),
                                                       v.w - __bfloat162float(h23.y));
            *(__nv_bfloat162*)&AsH[row][kq * 4]     = h01;
            *(__nv_bfloat162*)&AsH[row][kq * 4 + 2] = h23;
            *(__nv_bfloat162*)&AsL[row][kq * 4]     = l01;
            *(__nv_bfloat162*)&AsL[row][kq * 4 + 2] = l23;
        }
#pragma unroll
        for (int i = 0; i < 4; i++) {
            int id = tid + 256 * i;
            int kr = id >> 5, nq = id & 31;
            float4 v = *(const float4*)(Wb + (size_t)(k0 + kr) * HC_ + nq * 4);
            __nv_bfloat162 h01 = __floats2bfloat162_rn(v.x, v.y);
            __nv_bfloat162 h23 = __floats2bfloat162_rn(v.z, v.w);
            __nv_bfloat162 l01 = __floats2bfloat162_rn(v.x - __bfloat162float(h01.x),
                                                       v.y - __bfloat162float(h01.y));
            __nv_bfloat162 l23 = __floats2bfloat162_rn(v.z - __bfloat162float(h23.x),
                                                       v.w - __bfloat162float(h23.y));
            *(__nv_bfloat162*)&BsH[kr][nq * 4]     = h01;
            *(__nv_bfloat162*)&BsH[kr][nq * 4 + 2] = h23;
            *(__nv_bfloat162*)&BsL[kr][nq * 4]     = l01;
            *(__nv_bfloat162*)&BsL[kr][nq * 4 + 2] = l23;
        }
        __syncthreads();

#pragma unroll
        for (int ks = 0; ks < 2; ks++) {
            int kc = ks * 16;
            unsigned aH[2][4], aL[2][4];
            int ar = (seg & 1) * 8 + lrow;
            int ac = kc + (seg >> 1) * 8;
#pragma unroll
            for (int mt = 0; mt < 2; mt++) {
                int m = wr * 32 + mt * 16 + ar;
                ldsm4(aH[mt], sptr(&AsH[m][ac]));
                ldsm4(aL[mt], sptr(&AsL[m][ac]));
            }
            int br = kc + (seg & 1) * 8 + lrow;
            int bcoff = (seg >> 1) * 8;
#pragma unroll
            for (int ntp = 0; ntp < 4; ntp++) {
                int n0 = wc * 64 + ntp * 16 + bcoff;
                unsigned bH[4], bL[4];
                ldsm4t(bH, sptr(&BsH[br][n0]));
                ldsm4t(bL, sptr(&BsL[br][n0]));
#pragma unroll
                for (int half = 0; half < 2; half++) {
                    int nt = 2 * ntp + half;
                    unsigned b0H = bH[2 * half], b1H = bH[2 * half + 1];
                    unsigned b0L = bL[2 * half], b1L = bL[2 * half + 1];
#pragma unroll
                    for (int mt = 0; mt < 2; mt++) {
                        mma16(c[mt][nt], aH[mt], b0H, b1H);
                        mma16(c[mt][nt], aL[mt], b0H, b1H);
                        mma16(c[mt][nt], aH[mt], b0L, b1L);
                    }
                }
            }
        }
        __syncthreads();
    }

    int g4 = lid >> 2, t4 = lid & 3;

    // store fp16 transform output only (fp32 copy deleted — no remaining readers)
#pragma unroll
    for (int mt = 0; mt < 2; mt++) {
#pragma unroll
        for (int nt = 0; nt < 8; nt++) {
            int row = blockIdx.x * 128 + wr * 32 + mt * 16 + g4;
            int col = blockIdx.y * 128 + wc * 64 + nt * 8 + 2 * t4;
            *(__half2*)(g_xwh + (size_t)row * HC_ + col) =
                __floats2half2_rn(c[mt][nt][0], c[mt][nt][1]);
            *(__half2*)(g_xwh + (size_t)(row + 8) * HC_ + col) =
                __floats2half2_rn(c[mt][nt][2], c[mt][nt][3]);
        }
    }

    // fused attention dots (fp32 accumulators, exact)
    int head = blockIdx.y * 2 + wc;
    const float* Asv = att_s + head * 64;
    const float* Adv = att_d + head * 64;
#pragma unroll
    for (int mt = 0; mt < 2; mt++) {
        float s0 = 0.f, s1 = 0.f, d0 = 0.f, d1 = 0.f;
#pragma unroll
        for (int nt = 0; nt < 8; nt++) {
            int cb = nt * 8 + 2 * t4;
            float a0 = Asv[cb], a1 = Asv[cb + 1];
            float b0 = Adv[cb], b1 = Adv[cb + 1];
            s0 += c[mt][nt][0] * a0 + c[mt][nt][1] * a1;
            s1 += c[mt][nt][2] * a0 + c[mt][nt][3] * a1;
            d0 += c[mt][nt][0] * b0 + c[mt][nt][1] * b1;
            d1 += c[mt][nt][2] * b0 + c[mt][nt][3] * b1;
        }
#pragma unroll
        for (int off = 1; off <= 2; off <<= 1) {
            s0 += __shfl_xor_sync(0xffffffffu, s0, off);
            s1 += __shfl_xor_sync(0xffffffffu, s1, off);
            d0 += __shfl_xor_sync(0xffffffffu, d0, off);
            d1 += __shfl_xor_sync(0xffffffffu, d1, off);
        }
        if (t4 == 0) {
            int r = blockIdx.x * 128 + wr * 32 + mt * 16 + g4;
            g_asrc[r * 4 + head]       = s0;
            g_adst[r * 4 + head]       = d0;
            g_asrc[(r + 8) * 4 + head] = s1;
            g_adst[(r + 8) * 4 + head] = d1;
        }
    }
}

// ---------------- GAT aggregation (warp per node, fp16 gather, prefetch) ------
__global__ void k_agg(const float* __restrict__ bias,
                      const float* __restrict__ poolw,
                      const float* __restrict__ poolb,
                      int writeH, int seg) {
    int n = (blockIdx.x * blockDim.x + threadIdx.x) >> 5;
    int lane = threadIdx.x & 31;
    if (n >= NT_) return;
    int h = lane >> 3;

    float4 d4 = *(const float4*)(g_adst + n * 4);
    float4 s4 = *(const float4*)(g_asrc + n * 4);
    float adh = (h == 0) ? d4.x : (h == 1) ? d4.y : (h == 2) ? d4.z : d4.w;
    float ash = (h == 0) ? s4.x : (h == 1) ? s4.y : (h == 2) ? s4.z : s4.w;

    int r0 = g_row[n], r1 = g_row[n + 1];

    float wself = __expf(lrelu(ash + adh));
    float den = wself;
    // self-loop row from fp16 (same precision class as neighbor terms)
    uint4 qs = *(const uint4*)(g_xwh + (size_t)n * HC_ + lane * 8);
    float2 s0 = __half22float2(*(__half2*)&qs.x);
    float2 s1 = __half22float2(*(__half2*)&qs.y);
    float2 s2 = __half22float2(*(__half2*)&qs.z);
    float2 s3 = __half22float2(*(__half2*)&qs.w);
    float4 acc0 = {wself*s0.x, wself*s0.y, wself*s1.x, wself*s1.y};
    float4 acc1 = {wself*s2.x, wself*s2.y, wself*s3.x, wself*s3.y};

    int sN = 0; float asN = 0.f;
    if (r0 < r1) { sN = g_csr[r0]; asN = g_asrc[sN * 4 + h]; }
    for (int e = r0; e < r1; e++) {
        int s = sN; float as = asN;
        int eN = (e + 1 < r1) ? e + 1 : e;
        sN = g_csr[eN];
        asN = g_asrc[sN * 4 + h];
        float wgt = __expf(lrelu(as + adh));
        den += wgt;
        uint4 q = *(const uint4*)(g_xwh + (size_t)s * HC_ + lane * 8);
        float2 f0 = __half22float2(*(__half2*)&q.x);
        float2 f1 = __half22float2(*(__half2*)&q.y);
        float2 f2 = __half22float2(*(__half2*)&q.z);
        float2 f3 = __half22float2(*(__half2*)&q.w);
        acc0.x += wgt * f0.x; acc0.y += wgt * f0.y;
        acc0.z += wgt * f1.x; acc0.w += wgt * f1.y;
        acc1.x += wgt * f2.x; acc1.y += wgt * f2.y;
        acc1.z += wgt * f3.x; acc1.w += wgt * f3.y;
    }
    float rden = 1.f / (den + 1e-16f);
    acc0.x *= rden; acc0.y *= rden; acc0.z *= rden; acc0.w *= rden;
    acc1.x *= rden; acc1.y *= rden; acc1.z *= rden; acc1.w *= rden;

    const float* bp = bias + lane * 8;
    float v[8];
    v[0] = elu1(acc0.x + bp[0]); v[1] = elu1(acc0.y + bp[1]);
    v[2] = elu1(acc0.z + bp[2]); v[3] = elu1(acc0.w + bp[3]);
    v[4] = elu1(acc1.x + bp[4]); v[5] = elu1(acc1.y + bp[5]);
    v[6] = elu1(acc1.z + bp[6]); v[7] = elu1(acc1.w + bp[7]);

    if (writeH) {
        float4 o0 = {v[0], v[1], v[2], v[3]};
        float4 o1 = {v[4], v[5], v[6], v[7]};
        *(float4*)(g_h + (size_t)n * HC_ + lane * 8)     = o0;
        *(float4*)(g_h + (size_t)n * HC_ + lane * 8 + 4) = o1;
    }

    const float* pw = poolw + lane * 8;
    float p = v[0]*pw[0] + v[1]*pw[1] + v[2]*pw[2] + v[3]*pw[3]
            + v[4]*pw[4] + v[5]*pw[5] + v[6]*pw[6] + v[7]*pw[7];
#pragma unroll
    for (int off = 16; off >= 1; off >>= 1)
        p += __shfl_xor_sync(0xffffffffu, p, off);
    if (lane == 0)
        g_feat[(n >> 11) * (3 * N_) + seg * N_ + (n & 2047)] = p + poolb[0];
}

// ---------------- LayerNorm in place (48 rows) --------------------------------
__global__ void k_ln(const float* __restrict__ w, const float* __restrict__ b) {
    __shared__ float red[8];
    __shared__ float tot;
    int row = blockIdx.x;
    float* p = g_feat + (row / 3) * (3 * N_) + (row % 3) * N_;
    int t = threadIdx.x;
    float v[8];
    float s = 0.f;
#pragma unroll
    for (int i = 0; i < 8; i++) { v[i] = p[t + 256 * i]; s += v[i]; }
#pragma unroll
    for (int off = 16; off >= 1; off >>= 1) s += __shfl_xor_sync(0xffffffffu, s, off);
    if ((t & 31) == 0) red[t >> 5] = s;
    __syncthreads();
    if (t == 0) { float z = 0.f; for (int i = 0; i < 8; i++) z += red[i]; tot = z; }
    __syncthreads();
    float mu = tot * (1.f / 2048.f);
    float q = 0.f;
#pragma unroll
    for (int i = 0; i < 8; i++) { float d = v[i] - mu; q += d * d; }
#pragma unroll
    for (int off = 16; off >= 1; off >>= 1) q += __shfl_xor_sync(0xffffffffu, q, off);
    __syncthreads();
    if ((t & 31) == 0) red[t >> 5] = q;
    __syncthreads();
    if (t == 0) { float z = 0.f; for (int i = 0; i < 8; i++) z += red[i]; tot = z; }
    __syncthreads();
    float r = rsqrtf(tot * (1.f / 2048.f) + 1e-5f);
#pragma unroll
    for (int i = 0; i < 8; i++) {
        int idx = t + 256 * i;
        p[idx] = (v[i] - mu) * r * w[idx] + b[idx];
    }
}

// ---------------- fc0 partial GEMM (12 k-splits) ------------------------------
__global__ void k_fc0(const float* __restrict__ W) {
    __shared__ float sa[16][128];
    int tid = threadIdx.x;
    int j = blockIdx.x * 128 + tid;
    int k0 = blockIdx.y * 512;
    float acc[16];
#pragma unroll
    for (int bi = 0; bi < 16; bi++) acc[bi] = 0.f;
    for (int kt = k0; kt < k0 + 512; kt += 128) {
#pragma unroll
        for (int i = 0; i < 16; i++) sa[i][tid] = g_feat[i * (3 * N_) + kt + tid];
        __syncthreads();
#pragma unroll 8
        for (int kk = 0; kk < 128; kk++) {
            float wv = W[(size_t)(kt + kk) * FC0_ + j];
#pragma unroll
            for (int bi = 0; bi < 16; bi++) acc[bi] += sa[bi][kk] * wv;
        }
        __syncthreads();
    }
#pragma unroll
    for (int bi = 0; bi < 16; bi++)
        g_part[((size_t)blockIdx.y * 16 + bi) * FC0_ + j] = acc[bi];
}

// ---------------- fused FC tail: fcsum0 + fc1 + fc2 + last --------------------
__global__ __launch_bounds__(512)
void k_fctail(const float* __restrict__ e0b,
              const float* __restrict__ e1w, const float* __restrict__ e1b,
              const float* __restrict__ e2w, const float* __restrict__ e2b,
              const float* __restrict__ lw,  const float* __restrict__ lb,
              float* __restrict__ out, int out_n) {
    __shared__ float se0[FC0_];
    __shared__ float se1[FC1_];
    __shared__ float se2[OMIC_];
    int b = blockIdx.x;
    int t = threadIdx.x;

    for (int j = t; j < FC0_; j += 512) {
        float s = 0.f;
#pragma unroll
        for (int p = 0; p < 12; p++)
            s += g_part[((size_t)p * 16 + b) * FC0_ + j];
        se0[j] = elu1(s + e0b[j]);
    }
    __syncthreads();

    {
        float s = 0.f;
        for (int k = 0; k < FC0_; k++)
            s += se0[k] * e1w[(size_t)k * FC1_ + t];
        se1[t] = elu1(s + e1b[t]);
    }
    __syncthreads();

    if (t < OMIC_) {
        float s = 0.f;
        for (int k = 0; k < FC1_; k++)
            s += se1[k] * e2w[(size_t)k * OMIC_ + t];
        se2[t] = elu1(s + e2b[t]);
    }
    __syncthreads();

    if (t < OUT_) {
        float a = 0.f;
        for (int k = 0; k < OMIC_; k++) a += se2[k] * lw[k * OUT_ + t];
        int oi = b * OUT_ + t;
        if (oi < out_n) out[oi] = a + lb[t];
    }
}

// ---------------- driver --------------------------------------------------------
extern "C" void kernel_launch(void* const* d_in, const int* in_sizes, int n_in,
                              void* d_out, int out_size) {
    const float* x   = (const float*)d_in[0];
    const void*  ei  = d_in[1];
    const float* w1  = (const float*)d_in[2];
    const float* as1 = (const float*)d_in[3];
    const float* ad1 = (const float*)d_in[4];
    const float* b1  = (const float*)d_in[5];
    const float* p1w = (const float*)d_in[6];
    const float* p1b = (const float*)d_in[7];
    const float* w2  = (const float*)d_in[8];
    const float* as2 = (const float*)d_in[9];
    const float* ad2 = (const float*)d_in[10];
    const float* b2  = (const float*)d_in[11];
    const float* p2w = (const float*)d_in[12];
    const float* p2b = (const float*)d_in[13];
    const float* lnw = (const float*)d_in[14];
    const float* lnb = (const float*)d_in[15];
    const float* e0w = (const float*)d_in[16];
    const float* e0b = (const float*)d_in[17];
    const float* e1w = (const float*)d_in[18];
    const float* e1b = (const float*)d_in[19];
    const float* e2w = (const float*)d_in[20];
    const float* e2b = (const float*)d_in[21];
    const float* lw  = (const float*)d_in[22];
    const float* lb  = (const float*)d_in[23];
    float* out = (float*)d_out;

    k_zero<<<4096, 256>>>(ei, x);                                      // 1
    k_deg<<<E_ / 256, 256>>>(ei);                                      // 2
    k_scan1<<<128, 256>>>();                                           // 3
    k_gemm_tc<<<dim3(NT_ / 128, 2), 256>>>(x, 0, w1, INCH_, as1, ad1); // 4 <- profiled
    k_scan3b<<<128, 256>>>();                                          // 5
    k_scatter<<<E_ / 256, 256>>>(ei);                                  // 6
    k_sortseg<<<NT_ / 256, 256>>>();                                   // 7
    k_agg<<<NT_ / 8, 256>>>(b1, p1w, p1b, 1, 1);                       // 8
    k_gemm_tc<<<dim3(NT_ / 128, 2), 256>>>(nullptr, 1, w2, HC_, as2, ad2); // 9
    k_agg<<<NT_ / 8, 256>>>(b2, p2w, p2b, 0, 2);                       // 10
    k_ln<<<48, 256>>>(lnw, lnb);                                       // 11
    k_fc0<<<dim3(FC0_ / 128, 12), 128>>>(e0w);                         // 12
    k_fctail<<<B_, 512>>>(e0b, e1w, e1b, e2w, e2b, lw, lb, out, out_size); // 13
}

// round 15
// speedup vs baseline: 1.6139x; 1.0413x over previous
#include <cuda_runtime.h>
#include <cuda_fp16.h>
#include <cuda_bf16.h>
#include <math.h>

#define NT_   32768
#define B_    16
#define N_    2048
#define INCH_ 128
#define H_    4
#define C_    64
#define HC_   256
#define E_    524288
#define FC0_  1024
#define FC1_  512
#define OMIC_ 128
#define OUT_  2

// ---------------- scratch (static device globals) --------------------------
__device__ __align__(16) __half g_xwh[NT_ * HC_];            // fp16 transform output
__device__ __align__(16) __nv_bfloat16 g_xh[NT_ * INCH_];    // x hi/lo split
__device__ __align__(16) __nv_bfloat16 g_xl[NT_ * INCH_];
__device__ __align__(16) __nv_bfloat16 g_hh[NT_ * HC_];      // h hi/lo split
__device__ __align__(16) __nv_bfloat16 g_hl[NT_ * HC_];
__device__ __align__(16) __nv_bfloat16 g_w1h[INCH_ * HC_];
__device__ __align__(16) __nv_bfloat16 g_w1l[INCH_ * HC_];
__device__ __align__(16) __nv_bfloat16 g_w2h[HC_ * HC_];
__device__ __align__(16) __nv_bfloat16 g_w2l[HC_ * HC_];
__device__ __align__(16) float g_asrc[NT_ * 4];
__device__ __align__(16) float g_adst[NT_ * 4];
__device__ int   g_deg[NT_];
__device__ int   g_cur[NT_];
__device__ int   g_row[NT_ + 1];
__device__ int   g_blk[128];
__device__ int   g_csr[E_];
__device__ __align__(16) float g_feat[B_ * 3 * N_];
__device__ __align__(16) float g_part[12 * B_ * FC0_];
__device__ int   g_i64;

__device__ __forceinline__ float elu1(float x)  { return x > 0.f ? x : (expf(x) - 1.f); }
__device__ __forceinline__ float lrelu(float x) { return x > 0.f ? x : 0.2f * x; }

__device__ __forceinline__ int ld_idx(const void* ei, int i) {
    if (g_i64) return (int)((const long long*)ei)[i];
    return ((const int*)ei)[i];
}

__device__ __forceinline__ void split1(float v, __nv_bfloat16& hi, __nv_bfloat16& lo) {
    hi = __float2bfloat16_rn(v);
    lo = __float2bfloat16_rn(v - __bfloat162float(hi));
}

// ---------------- zero + detect + x0 + x/w splits (fused) --------------------
__global__ void k_zero(const void* ei, const float* __restrict__ x,
                       const float* __restrict__ w1, const float* __restrict__ w2) {
    int tid = blockIdx.x * blockDim.x + threadIdx.x;   // 1,048,576 threads
    if (tid < NT_) { g_deg[tid] = 0; g_cur[tid] = 0; }
    if (blockIdx.x == 0 && threadIdx.x < 32) {
        const long long* p64 = (const long long*)ei;
        long long v = p64[threadIdx.x];
        unsigned bad = __ballot_sync(0xffffffffu, v < 0 || v >= NT_);
        if (threadIdx.x == 0) g_i64 = (bad == 0);
    }
    // weight splits
    if (tid < INCH_ * HC_) {
        __nv_bfloat16 hi, lo; split1(w1[tid], hi, lo);
        g_w1h[tid] = hi; g_w1l[tid] = lo;
    }
    if (tid < HC_ * HC_) {
        __nv_bfloat16 hi, lo; split1(w2[tid], hi, lo);
        g_w2h[tid] = hi; g_w2l[tid] = lo;
    }
    // x0 mean + x split (one warp per node; each lane owns 4 channels)
    int n = tid >> 5;
    int lane = threadIdx.x & 31;
    if (n < NT_) {
        float4 v = *(const float4*)(x + (size_t)n * INCH_ + lane * 4);
        __nv_bfloat162 h01 = __floats2bfloat162_rn(v.x, v.y);
        __nv_bfloat162 h23 = __floats2bfloat162_rn(v.z, v.w);
        __nv_bfloat162 l01 = __floats2bfloat162_rn(v.x - __bfloat162float(h01.x),
                                                   v.y - __bfloat162float(h01.y));
        __nv_bfloat162 l23 = __floats2bfloat162_rn(v.z - __bfloat162float(h23.x),
                                                   v.w - __bfloat162float(h23.y));
        size_t o = (size_t)n * INCH_ + lane * 4;
        *(__nv_bfloat162*)(g_xh + o)     = h01;
        *(__nv_bfloat162*)(g_xh + o + 2) = h23;
        *(__nv_bfloat162*)(g_xl + o)     = l01;
        *(__nv_bfloat162*)(g_xl + o + 2) = l23;
        float s = v.x + v.y + v.z + v.w;
#pragma unroll
        for (int off = 16; off >= 1; off >>= 1)
            s += __shfl_xor_sync(0xffffffffu, s, off);
        if (lane == 0)
            g_feat[(n >> 11) * (3 * N_) + (n & 2047)] = s * (1.f / 128.f);
    }
}

__global__ void k_deg(const void* __restrict__ ei) {
    int e = blockIdx.x * blockDim.x + threadIdx.x;
    if (e < E_) atomicAdd(&g_deg[ld_idx(ei, E_ + e) & (NT_ - 1)], 1);
}

__global__ void k_scan1() {
    __shared__ int wt[8];
    int t = threadIdx.x;
    int i = blockIdx.x * 256 + t;
    int v = g_deg[i];
    int lane = t & 31, w = t >> 5;
    int inc = v;
#pragma unroll
    for (int off = 1; off < 32; off <<= 1) {
        int u = __shfl_up_sync(0xffffffffu, inc, off);
        if (lane >= off) inc += u;
    }
    if (lane == 31) wt[w] = inc;
    __syncthreads();
    if (t == 0) {
        int run = 0;
#pragma unroll
        for (int k = 0; k < 8; k++) { int x = wt[k]; wt[k] = run; run += x; }
        g_blk[blockIdx.x] = run;
    }
    __syncthreads();
    g_row[i] = inc - v + wt[w];
}

__global__ void k_scan3b() {
    __shared__ int part[4];
    int t = threadIdx.x;
    int v = (t < 128 && t < blockIdx.x) ? g_blk[t] : 0;
    if (t < 128) {
        int u = v;
#pragma unroll
        for (int off = 16; off >= 1; off >>= 1)
            u += __shfl_xor_sync(0xffffffffu, u, off);
        if ((t & 31) == 0) part[t >> 5] = u;
    }
    __syncthreads();
    int pre = part[0] + part[1] + part[2] + part[3];
    g_row[blockIdx.x * 256 + t] += pre;
    if (blockIdx.x == 127 && t == 255) g_row[NT_] = pre + g_blk[127];
}

__global__ void k_scatter(const void* __restrict__ ei) {
    int e = blockIdx.x * blockDim.x + threadIdx.x;
    if (e < E_) {
        int d = ld_idx(ei, E_ + e) & (NT_ - 1);
        int s = ld_idx(ei, e) & (NT_ - 1);
        int pos = g_row[d] + atomicAdd(&g_cur[d], 1);
        g_csr[pos] = s;
    }
}

__global__ void k_sortseg() {
    int n = blockIdx.x * blockDim.x + threadIdx.x;
    if (n >= NT_) return;
    int r0 = g_row[n], r1 = g_row[n + 1];
    int len = r1 - r0;
    if (len <= 1) return;
    if (len <= 96) {
        int buf[96];
        for (int i = 0; i < len; i++) buf[i] = g_csr[r0 + i];
        for (int i = 1; i < len; i++) {
            int v = buf[i]; int j = i - 1;
            while (j >= 0 && buf[j] > v) { buf[j + 1] = buf[j]; j--; }
            buf[j + 1] = v;
        }
        for (int i = 0; i < len; i++) g_csr[r0 + i] = buf[i];
    } else {
        for (int i = r0 + 1; i < r1; i++) {
            int v = g_csr[i]; int j = i - 1;
            while (j >= r0 && g_csr[j] > v) { g_csr[j + 1] = g_csr[j]; j--; }
            g_csr[j + 1] = v;
        }
    }
}

// ---------------- bf16 3-pass tensor GEMM (pre-split operands) ----------------
__device__ __forceinline__ void mma16(float* c, const unsigned* a,
                                      unsigned b0, unsigned b1) {
    asm volatile(
        "mma.sync.aligned.m16n8k16.row.col.f32.bf16.bf16.f32 "
        "{%0,%1,%2,%3},{%4,%5,%6,%7},{%8,%9},{%0,%1,%2,%3};"
        : "+f"(c[0]), "+f"(c[1]), "+f"(c[2]), "+f"(c[3])
        : "r"(a[0]), "r"(a[1]), "r"(a[2]), "r"(a[3]), "r"(b0), "r"(b1));
}

__device__ __forceinline__ unsigned sptr(const void* p) {
    return (unsigned)__cvta_generic_to_shared(p);
}

__device__ __forceinline__ void ldsm4(unsigned* r, unsigned addr) {
    asm volatile("ldmatrix.sync.aligned.m8n8.x4.shared.b16 {%0,%1,%2,%3}, [%4];"
                 : "=r"(r[0]), "=r"(r[1]), "=r"(r[2]), "=r"(r[3]) : "r"(addr));
}

__device__ __forceinline__ void ldsm4t(unsigned* r, unsigned addr) {
    asm volatile("ldmatrix.sync.aligned.m8n8.x4.trans.shared.b16 {%0,%1,%2,%3}, [%4];"
                 : "=r"(r[0]), "=r"(r[1]), "=r"(r[2]), "=r"(r[3]) : "r"(addr));
}

__global__ __launch_bounds__(256, 2)
void k_gemm_tc(int useH, int K,
               const float* __restrict__ att_s, const float* __restrict__ att_d) {
    const __nv_bfloat16* Ah = useH ? g_hh : g_xh;
    const __nv_bfloat16* Al = useH ? g_hl : g_xl;
    const __nv_bfloat16* Wh = useH ? g_w2h : g_w1h;
    const __nv_bfloat16* Wl = useH ? g_w2l : g_w1l;
    __shared__ __nv_bfloat16 AsH[128][40];
    __shared__ __nv_bfloat16 AsL[128][40];
    __shared__ __nv_bfloat16 BsH[32][136];
    __shared__ __nv_bfloat16 BsL[32][136];
    int tid = threadIdx.x;
    int lid = tid & 31, wid = tid >> 5;
    int wr = wid >> 1, wc = wid & 1;
    int lrow = lid & 7, seg = lid >> 3;

    const __nv_bfloat16* Abh = Ah + (size_t)blockIdx.x * 128 * K;
    const __nv_bfloat16* Abl = Al + (size_t)blockIdx.x * 128 * K;
    int bn0 = blockIdx.y * 128;

    float c[2][8][4];
#pragma unroll
    for (int mt = 0; mt < 2; mt++)
#pragma unroll
        for (int nt = 0; nt < 8; nt++)
#pragma unroll
            for (int q = 0; q < 4; q++) c[mt][nt][q] = 0.f;

    for (int k0 = 0; k0 < K; k0 += 32) {
        // A tile 128x32 bf16 hi/lo: pure uint4 copies
#pragma unroll
        for (int i = 0; i < 2; i++) {
            int id = tid + 256 * i;          // 0..511
            int row = id >> 2, sq = id & 3;
            uint4 vh = *(const uint4*)(Abh + (size_t)row * K + k0 + sq * 8);
            uint4 vl = *(const uint4*)(Abl + (size_t)row * K + k0 + sq * 8);
            *(uint4*)&AsH[row][sq * 8] = vh;
            *(uint4*)&AsL[row][sq * 8] = vl;
        }
        // B tile 32x128 bf16 hi/lo
#pragma unroll
        for (int i = 0; i < 2; i++) {
            int id = tid + 256 * i;          // 0..511
            int kr = id >> 4, nq = id & 15;
            uint4 vh = *(const uint4*)(Wh + (size_t)(k0 + kr) * HC_ + bn0 + nq * 8);
            uint4 vl = *(const uint4*)(Wl + (size_t)(k0 + kr) * HC_ + bn0 + nq * 8);
            *(uint4*)&BsH[kr][nq * 8] = vh;
            *(uint4*)&BsL[kr][nq * 8] = vl;
        }
        __syncthreads();

#pragma unroll
        for (int ks = 0; ks < 2; ks++) {
            int kc = ks * 16;
            unsigned aH[2][4], aL[2][4];
            int ar = (seg & 1) * 8 + lrow;
            int ac = kc + (seg >> 1) * 8;
#pragma unroll
            for (int mt = 0; mt < 2; mt++) {
                int m = wr * 32 + mt * 16 + ar;
                ldsm4(aH[mt], sptr(&AsH[m][ac]));
                ldsm4(aL[mt], sptr(&AsL[m][ac]));
            }
            int br = kc + (seg & 1) * 8 + lrow;
            int bcoff = (seg >> 1) * 8;
#pragma unroll
            for (int ntp = 0; ntp < 4; ntp++) {
                int n0 = wc * 64 + ntp * 16 + bcoff;
                unsigned bH[4], bL[4];
                ldsm4t(bH, sptr(&BsH[br][n0]));
                ldsm4t(bL, sptr(&BsL[br][n0]));
#pragma unroll
                for (int half = 0; half < 2; half++) {
                    int nt = 2 * ntp + half;
                    unsigned b0H = bH[2 * half], b1H = bH[2 * half + 1];
                    unsigned b0L = bL[2 * half], b1L = bL[2 * half + 1];
#pragma unroll
                    for (int mt = 0; mt < 2; mt++) {
                        mma16(c[mt][nt], aH[mt], b0H, b1H);
                        mma16(c[mt][nt], aL[mt], b0H, b1H);
                        mma16(c[mt][nt], aH[mt], b0L, b1L);
                    }
                }
            }
        }
        __syncthreads();
    }

    int g4 = lid >> 2, t4 = lid & 3;

    // store fp16 transform output
#pragma unroll
    for (int mt = 0; mt < 2; mt++) {
#pragma unroll
        for (int nt = 0; nt < 8; nt++) {
            int row = blockIdx.x * 128 + wr * 32 + mt * 16 + g4;
            int col = bn0 + wc * 64 + nt * 8 + 2 * t4;
            *(__half2*)(g_xwh + (size_t)row * HC_ + col) =
                __floats2half2_rn(c[mt][nt][0], c[mt][nt][1]);
            *(__half2*)(g_xwh + (size_t)(row + 8) * HC_ + col) =
                __floats2half2_rn(c[mt][nt][2], c[mt][nt][3]);
        }
    }

    // fused attention dots (fp32 accumulators, exact)
    int head = blockIdx.y * 2 + wc;
    const float* Asv = att_s + head * 64;
    const float* Adv = att_d + head * 64;
#pragma unroll
    for (int mt = 0; mt < 2; mt++) {
        float s0 = 0.f, s1 = 0.f, d0 = 0.f, d1 = 0.f;
#pragma unroll
        for (int nt = 0; nt < 8; nt++) {
            int cb = nt * 8 + 2 * t4;
            float a0 = Asv[cb], a1 = Asv[cb + 1];
            float b0 = Adv[cb], b1 = Adv[cb + 1];
            s0 += c[mt][nt][0] * a0 + c[mt][nt][1] * a1;
            s1 += c[mt][nt][2] * a0 + c[mt][nt][3] * a1;
            d0 += c[mt][nt][0] * b0 + c[mt][nt][1] * b1;
            d1 += c[mt][nt][2] * b0 + c[mt][nt][3] * b1;
        }
#pragma unroll
        for (int off = 1; off <= 2; off <<= 1) {
            s0 += __shfl_xor_sync(0xffffffffu, s0, off);
            s1 += __shfl_xor_sync(0xffffffffu, s1, off);
            d0 += __shfl_xor_sync(0xffffffffu, d0, off);
            d1 += __shfl_xor_sync(0xffffffffu, d1, off);
        }
        if (t4 == 0) {
            int r = blockIdx.x * 128 + wr * 32 + mt * 16 + g4;
            g_asrc[r * 4 + head]       = s0;
            g_adst[r * 4 + head]       = d0;
            g_asrc[(r + 8) * 4 + head] = s1;
            g_adst[(r + 8) * 4 + head] = d1;
        }
    }
}

// ---------------- GAT aggregation (warp per node, fp16 gather, prefetch) ------
__global__ void k_agg(const float* __restrict__ bias,
                      const float* __restrict__ poolw,
                      const float* __restrict__ poolb,
                      int writeH, int seg) {
    int n = (blockIdx.x * blockDim.x + threadIdx.x) >> 5;
    int lane = threadIdx.x & 31;
    if (n >= NT_) return;
    int h = lane >> 3;

    float4 d4 = *(const float4*)(g_adst + n * 4);
    float4 s4 = *(const float4*)(g_asrc + n * 4);
    float adh = (h == 0) ? d4.x : (h == 1) ? d4.y : (h == 2) ? d4.z : d4.w;
    float ash = (h == 0) ? s4.x : (h == 1) ? s4.y : (h == 2) ? s4.z : s4.w;

    int r0 = g_row[n], r1 = g_row[n + 1];

    float wself = __expf(lrelu(ash + adh));
    float den = wself;
    uint4 qs = *(const uint4*)(g_xwh + (size_t)n * HC_ + lane * 8);
    float2 s0 = __half22float2(*(__half2*)&qs.x);
    float2 s1 = __half22float2(*(__half2*)&qs.y);
    float2 s2 = __half22float2(*(__half2*)&qs.z);
    float2 s3 = __half22float2(*(__half2*)&qs.w);
    float4 acc0 = {wself*s0.x, wself*s0.y, wself*s1.x, wself*s1.y};
    float4 acc1 = {wself*s2.x, wself*s2.y, wself*s3.x, wself*s3.y};

    int sN = 0; float asN = 0.f;
    if (r0 < r1) { sN = g_csr[r0]; asN = g_asrc[sN * 4 + h]; }
    for (int e = r0; e < r1; e++) {
        int s = sN; float as = asN;
        int eN = (e + 1 < r1) ? e + 1 : e;
        sN = g_csr[eN];
        asN = g_asrc[sN * 4 + h];
        float wgt = __expf(lrelu(as + adh));
        den += wgt;
        uint4 q = *(const uint4*)(g_xwh + (size_t)s * HC_ + lane * 8);
        float2 f0 = __half22float2(*(__half2*)&q.x);
        float2 f1 = __half22float2(*(__half2*)&q.y);
        float2 f2 = __half22float2(*(__half2*)&q.z);
        float2 f3 = __half22float2(*(__half2*)&q.w);
        acc0.x += wgt * f0.x; acc0.y += wgt * f0.y;
        acc0.z += wgt * f1.x; acc0.w += wgt * f1.y;
        acc1.x += wgt * f2.x; acc1.y += wgt * f2.y;
        acc1.z += wgt * f3.x; acc1.w += wgt * f3.y;
    }
    float rden = 1.f / (den + 1e-16f);
    acc0.x *= rden; acc0.y *= rden; acc0.z *= rden; acc0.w *= rden;
    acc1.x *= rden; acc1.y *= rden; acc1.z *= rden; acc1.w *= rden;

    const float* bp = bias + lane * 8;
    float v[8];
    v[0] = elu1(acc0.x + bp[0]); v[1] = elu1(acc0.y + bp[1]);
    v[2] = elu1(acc0.z + bp[2]); v[3] = elu1(acc0.w + bp[3]);
    v[4] = elu1(acc1.x + bp[4]); v[5] = elu1(acc1.y + bp[5]);
    v[6] = elu1(acc1.z + bp[6]); v[7] = elu1(acc1.w + bp[7]);

    if (writeH) {
        // write h as pre-split bf16 hi/lo for gemm2
        __nv_bfloat162 hh[4], hl[4];
#pragma unroll
        for (int j = 0; j < 4; j++) {
            __nv_bfloat162 hi = __floats2bfloat162_rn(v[2*j], v[2*j+1]);
            __nv_bfloat162 lo = __floats2bfloat162_rn(
                v[2*j]   - __bfloat162float(hi.x),
                v[2*j+1] - __bfloat162float(hi.y));
            hh[j] = hi; hl[j] = lo;
        }
        *(uint4*)(g_hh + (size_t)n * HC_ + lane * 8) = *(uint4*)hh;
        *(uint4*)(g_hl + (size_t)n * HC_ + lane * 8) = *(uint4*)hl;
    }

    const float* pw = poolw + lane * 8;
    float p = v[0]*pw[0] + v[1]*pw[1] + v[2]*pw[2] + v[3]*pw[3]
            + v[4]*pw[4] + v[5]*pw[5] + v[6]*pw[6] + v[7]*pw[7];
#pragma unroll
    for (int off = 16; off >= 1; off >>= 1)
        p += __shfl_xor_sync(0xffffffffu, p, off);
    if (lane == 0)
        g_feat[(n >> 11) * (3 * N_) + seg * N_ + (n & 2047)] = p + poolb[0];
}

// ---------------- LayerNorm in place (48 rows) --------------------------------
__global__ void k_ln(const float* __restrict__ w, const float* __restrict__ b) {
    __shared__ float red[8];
    __shared__ float tot;
    int row = blockIdx.x;
    float* p = g_feat + (row / 3) * (3 * N_) + (row % 3) * N_;
    int t = threadIdx.x;
    float v[8];
    float s = 0.f;
#pragma unroll
    for (int i = 0; i < 8; i++) { v[i] = p[t + 256 * i]; s += v[i]; }
#pragma unroll
    for (int off = 16; off >= 1; off >>= 1) s += __shfl_xor_sync(0xffffffffu, s, off);
    if ((t & 31) == 0) red[t >> 5] = s;
    __syncthreads();
    if (t == 0) { float z = 0.f; for (int i = 0; i < 8; i++) z += red[i]; tot = z; }
    __syncthreads();
    float mu = tot * (1.f / 2048.f);
    float q = 0.f;
#pragma unroll
    for (int i = 0; i < 8; i++) { float d = v[i] - mu; q += d * d; }
#pragma unroll
    for (int off = 16; off >= 1; off >>= 1) q += __shfl_xor_sync(0xffffffffu, q, off);
    __syncthreads();
    if ((t & 31) == 0) red[t >> 5] = q;
    __syncthreads();
    if (t == 0) { float z = 0.f; for (int i = 0; i < 8; i++) z += red[i]; tot = z; }
    __syncthreads();
    float r = rsqrtf(tot * (1.f / 2048.f) + 1e-5f);
#pragma unroll
    for (int i = 0; i < 8; i++) {
        int idx = t + 256 * i;
        p[idx] = (v[i] - mu) * r * w[idx] + b[idx];
    }
}

// ---------------- fc0 partial GEMM (12 k-splits) ------------------------------
__global__ void k_fc0(const float* __restrict__ W) {
    __shared__ float sa[16][128];
    int tid = threadIdx.x;
    int j = blockIdx.x * 128 + tid;
    int k0 = blockIdx.y * 512;
    float acc[16];
#pragma unroll
    for (int bi = 0; bi < 16; bi++) acc[bi] = 0.f;
    for (int kt = k0; kt < k0 + 512; kt += 128) {
#pragma unroll
        for (int i = 0; i < 16; i++) sa[i][tid] = g_feat[i * (3 * N_) + kt + tid];
        __syncthreads();
#pragma unroll 8
        for (int kk = 0; kk < 128; kk++) {
            float wv = W[(size_t)(kt + kk) * FC0_ + j];
#pragma unroll
            for (int bi = 0; bi < 16; bi++) acc[bi] += sa[bi][kk] * wv;
        }
        __syncthreads();
    }
#pragma unroll
    for (int bi = 0; bi < 16; bi++)
        g_part[((size_t)blockIdx.y * 16 + bi) * FC0_ + j] = acc[bi];
}

// ---------------- fused FC tail --------------------------------------------------
__global__ __launch_bounds__(512)
void k_fctail(const float* __restrict__ e0b,
              const float* __restrict__ e1w, const float* __restrict__ e1b,
              const float* __restrict__ e2w, const float* __restrict__ e2b,
              const float* __restrict__ lw,  const float* __restrict__ lb,
              float* __restrict__ out, int out_n) {
    __shared__ float se0[FC0_];
    __shared__ float se1[FC1_];
    __shared__ float se2[OMIC_];
    int b = blockIdx.x;
    int t = threadIdx.x;

    for (int j = t; j < FC0_; j += 512) {
        float s = 0.f;
#pragma unroll
        for (int p = 0; p < 12; p++)
            s += g_part[((size_t)p * 16 + b) * FC0_ + j];
        se0[j] = elu1(s + e0b[j]);
    }
    __syncthreads();

    {
        float s = 0.f;
        for (int k = 0; k < FC0_; k++)
            s += se0[k] * e1w[(size_t)k * FC1_ + t];
        se1[t] = elu1(s + e1b[t]);
    }
    __syncthreads();

    if (t < OMIC_) {
        float s = 0.f;
        for (int k = 0; k < FC1_; k++)
            s += se1[k] * e2w[(size_t)k * OMIC_ + t];
        se2[t] = elu1(s + e2b[t]);
    }
    __syncthreads();

    if (t < OUT_) {
        float a = 0.f;
        for (int k = 0; k < OMIC_; k++) a += se2[k] * lw[k * OUT_ + t];
        int oi = b * OUT_ + t;
        if (oi < out_n) out[oi] = a + lb[t];
    }
}

// ---------------- driver ----------------------------------------------------------
extern "C" void kernel_launch(void* const* d_in, const int* in_sizes, int n_in,
                              void* d_out, int out_size) {
    const float* x   = (const float*)d_in[0];
    const void*  ei  = d_in[1];
    const float* w1  = (const float*)d_in[2];
    const float* as1 = (const float*)d_in[3];
    const float* ad1 = (const float*)d_in[4];
    const float* b1  = (const float*)d_in[5];
    const float* p1w = (const float*)d_in[6];
    const float* p1b = (const float*)d_in[7];
    const float* w2  = (const float*)d_in[8];
    const float* as2 = (const float*)d_in[9];
    const float* ad2 = (const float*)d_in[10];
    const float* b2  = (const float*)d_in[11];
    const float* p2w = (const float*)d_in[12];
    const float* p2b = (const float*)d_in[13];
    const float* lnw = (const float*)d_in[14];
    const float* lnb = (const float*)d_in[15];
    const float* e0w = (const float*)d_in[16];
    const float* e0b = (const float*)d_in[17];
    const float* e1w = (const float*)d_in[18];
    const float* e1b = (const float*)d_in[19];
    const float* e2w = (const float*)d_in[20];
    const float* e2b = (const float*)d_in[21];
    const float* lw  = (const float*)d_in[22];
    const float* lb  = (const float*)d_in[23];
    float* out = (float*)d_out;

    k_zero<<<4096, 256>>>(ei, x, w1, w2);                              // 1
    k_deg<<<E_ / 256, 256>>>(ei);                                      // 2
    k_scan1<<<128, 256>>>();                                           // 3
    k_gemm_tc<<<dim3(NT_ / 128, 2), 256>>>(0, INCH_, as1, ad1);        // 4 <- profiled
    k_scan3b<<<128, 256>>>();                                          // 5
    k_scatter<<<E_ / 256, 256>>>(ei);                                  // 6
    k_sortseg<<<NT_ / 256, 256>>>();                                   // 7
    k_agg<<<NT_ / 8, 256>>>(b1, p1w, p1b, 1, 1);                       // 8
    k_gemm_tc<<<dim3(NT_ / 128, 2), 256>>>(1, HC_, as2, ad2);          // 9
    k_agg<<<NT_ / 8, 256>>>(b2, p2w, p2b, 0, 2);                       // 10
    k_ln<<<48, 256>>>(lnw, lnb);                                       // 11
    k_fc0<<<dim3(FC0_ / 128, 12), 128>>>(e0w);                         // 12
    k_fctail<<<B_, 512>>>(e0b, e1w, e1b, e2w, e2b, lw, lb, out, out_size); // 13
}

// round 16
// speedup vs baseline: 1.8337x; 1.1362x over previous
#include <cuda_runtime.h>
#include <cuda_fp16.h>
#include <cuda_bf16.h>
#include <math.h>

#define NT_   32768
#define B_    16
#define N_    2048
#define INCH_ 128
#define H_    4
#define C_    64
#define HC_   256
#define E_    524288
#define FC0_  1024
#define FC1_  512
#define OMIC_ 128
#define OUT_  2
#define NSPLIT_ 24

// ---------------- scratch (static device globals) --------------------------
__device__ __align__(16) __half g_xwh[NT_ * HC_];            // fp16 transform output
__device__ __align__(16) __nv_bfloat16 g_xh[NT_ * INCH_];    // x hi/lo split
__device__ __align__(16) __nv_bfloat16 g_xl[NT_ * INCH_];
__device__ __align__(16) __nv_bfloat16 g_hh[NT_ * HC_];      // h hi/lo split
__device__ __align__(16) __nv_bfloat16 g_hl[NT_ * HC_];
__device__ __align__(16) __nv_bfloat16 g_w1h[INCH_ * HC_];
__device__ __align__(16) __nv_bfloat16 g_w1l[INCH_ * HC_];
__device__ __align__(16) __nv_bfloat16 g_w2h[HC_ * HC_];
__device__ __align__(16) __nv_bfloat16 g_w2l[HC_ * HC_];
__device__ __align__(16) float g_asrc[NT_ * 4];
__device__ __align__(16) float g_adst[NT_ * 4];
__device__ int   g_deg[NT_];
__device__ int   g_cur[NT_];
__device__ int   g_row[NT_ + 1];
__device__ int   g_blk[128];
__device__ int   g_csr[E_];
__device__ __align__(16) float g_feat[B_ * 3 * N_];
__device__ __align__(16) float g_part[NSPLIT_ * B_ * FC0_];
__device__ int   g_i64;

__device__ __forceinline__ float elu1(float x)  { return x > 0.f ? x : (expf(x) - 1.f); }
__device__ __forceinline__ float lrelu(float x) { return x > 0.f ? x : 0.2f * x; }

__device__ __forceinline__ int ld_idx(const void* ei, int i) {
    if (g_i64) return (int)((const long long*)ei)[i];
    return ((const int*)ei)[i];
}

__device__ __forceinline__ void split1(float v, __nv_bfloat16& hi, __nv_bfloat16& lo) {
    hi = __float2bfloat16_rn(v);
    lo = __float2bfloat16_rn(v - __bfloat162float(hi));
}

// ---------------- zero + detect + x0 + x/w splits (fused) --------------------
__global__ void k_zero(const void* ei, const float* __restrict__ x,
                       const float* __restrict__ w1, const float* __restrict__ w2) {
    int tid = blockIdx.x * blockDim.x + threadIdx.x;   // 1,048,576 threads
    if (tid < NT_) { g_deg[tid] = 0; g_cur[tid] = 0; }
    if (blockIdx.x == 0 && threadIdx.x < 32) {
        const long long* p64 = (const long long*)ei;
        long long v = p64[threadIdx.x];
        unsigned bad = __ballot_sync(0xffffffffu, v < 0 || v >= NT_);
        if (threadIdx.x == 0) g_i64 = (bad == 0);
    }
    if (tid < INCH_ * HC_) {
        __nv_bfloat16 hi, lo; split1(w1[tid], hi, lo);
        g_w1h[tid] = hi; g_w1l[tid] = lo;
    }
    if (tid < HC_ * HC_) {
        __nv_bfloat16 hi, lo; split1(w2[tid], hi, lo);
        g_w2h[tid] = hi; g_w2l[tid] = lo;
    }
    int n = tid >> 5;
    int lane = threadIdx.x & 31;
    if (n < NT_) {
        float4 v = *(const float4*)(x + (size_t)n * INCH_ + lane * 4);
        __nv_bfloat162 h01 = __floats2bfloat162_rn(v.x, v.y);
        __nv_bfloat162 h23 = __floats2bfloat162_rn(v.z, v.w);
        __nv_bfloat162 l01 = __floats2bfloat162_rn(v.x - __bfloat162float(h01.x),
                                                   v.y - __bfloat162float(h01.y));
        __nv_bfloat162 l23 = __floats2bfloat162_rn(v.z - __bfloat162float(h23.x),
                                                   v.w - __bfloat162float(h23.y));
        size_t o = (size_t)n * INCH_ + lane * 4;
        *(__nv_bfloat162*)(g_xh + o)     = h01;
        *(__nv_bfloat162*)(g_xh + o + 2) = h23;
        *(__nv_bfloat162*)(g_xl + o)     = l01;
        *(__nv_bfloat162*)(g_xl + o + 2) = l23;
        float s = v.x + v.y + v.z + v.w;
#pragma unroll
        for (int off = 16; off >= 1; off >>= 1)
            s += __shfl_xor_sync(0xffffffffu, s, off);
        if (lane == 0)
            g_feat[(n >> 11) * (3 * N_) + (n & 2047)] = s * (1.f / 128.f);
    }
}

__global__ void k_deg(const void* __restrict__ ei) {
    int e = blockIdx.x * blockDim.x + threadIdx.x;
    if (e < E_) atomicAdd(&g_deg[ld_idx(ei, E_ + e) & (NT_ - 1)], 1);
}

__global__ void k_scan1() {
    __shared__ int wt[8];
    int t = threadIdx.x;
    int i = blockIdx.x * 256 + t;
    int v = g_deg[i];
    int lane = t & 31, w = t >> 5;
    int inc = v;
#pragma unroll
    for (int off = 1; off < 32; off <<= 1) {
        int u = __shfl_up_sync(0xffffffffu, inc, off);
        if (lane >= off) inc += u;
    }
    if (lane == 31) wt[w] = inc;
    __syncthreads();
    if (t == 0) {
        int run = 0;
#pragma unroll
        for (int k = 0; k < 8; k++) { int x = wt[k]; wt[k] = run; run += x; }
        g_blk[blockIdx.x] = run;
    }
    __syncthreads();
    g_row[i] = inc - v + wt[w];
}

__global__ void k_scan3b() {
    __shared__ int part[4];
    int t = threadIdx.x;
    int v = (t < 128 && t < blockIdx.x) ? g_blk[t] : 0;
    if (t < 128) {
        int u = v;
#pragma unroll
        for (int off = 16; off >= 1; off >>= 1)
            u += __shfl_xor_sync(0xffffffffu, u, off);
        if ((t & 31) == 0) part[t >> 5] = u;
    }
    __syncthreads();
    int pre = part[0] + part[1] + part[2] + part[3];
    g_row[blockIdx.x * 256 + t] += pre;
    if (blockIdx.x == 127 && t == 255) g_row[NT_] = pre + g_blk[127];
}

__global__ void k_scatter(const void* __restrict__ ei) {
    int e = blockIdx.x * blockDim.x + threadIdx.x;
    if (e < E_) {
        int d = ld_idx(ei, E_ + e) & (NT_ - 1);
        int s = ld_idx(ei, e) & (NT_ - 1);
        int pos = g_row[d] + atomicAdd(&g_cur[d], 1);
        g_csr[pos] = s;
    }
}

__global__ void k_sortseg() {
    int n = blockIdx.x * blockDim.x + threadIdx.x;
    if (n >= NT_) return;
    int r0 = g_row[n], r1 = g_row[n + 1];
    int len = r1 - r0;
    if (len <= 1) return;
    if (len <= 96) {
        int buf[96];
        for (int i = 0; i < len; i++) buf[i] = g_csr[r0 + i];
        for (int i = 1; i < len; i++) {
            int v = buf[i]; int j = i - 1;
            while (j >= 0 && buf[j] > v) { buf[j + 1] = buf[j]; j--; }
            buf[j + 1] = v;
        }
        for (int i = 0; i < len; i++) g_csr[r0 + i] = buf[i];
    } else {
        for (int i = r0 + 1; i < r1; i++) {
            int v = g_csr[i]; int j = i - 1;
            while (j >= r0 && g_csr[j] > v) { g_csr[j + 1] = g_csr[j]; j--; }
            g_csr[j + 1] = v;
        }
    }
}

// ---------------- bf16 3-pass tensor GEMM (pre-split operands) ----------------
__device__ __forceinline__ void mma16(float* c, const unsigned* a,
                                      unsigned b0, unsigned b1) {
    asm volatile(
        "mma.sync.aligned.m16n8k16.row.col.f32.bf16.bf16.f32 "
        "{%0,%1,%2,%3},{%4,%5,%6,%7},{%8,%9},{%0,%1,%2,%3};"
        : "+f"(c[0]), "+f"(c[1]), "+f"(c[2]), "+f"(c[3])
        : "r"(a[0]), "r"(a[1]), "r"(a[2]), "r"(a[3]), "r"(b0), "r"(b1));
}

__device__ __forceinline__ unsigned sptr(const void* p) {
    return (unsigned)__cvta_generic_to_shared(p);
}

__device__ __forceinline__ void ldsm4(unsigned* r, unsigned addr) {
    asm volatile("ldmatrix.sync.aligned.m8n8.x4.shared.b16 {%0,%1,%2,%3}, [%4];"
                 : "=r"(r[0]), "=r"(r[1]), "=r"(r[2]), "=r"(r[3]) : "r"(addr));
}

__device__ __forceinline__ void ldsm4t(unsigned* r, unsigned addr) {
    asm volatile("ldmatrix.sync.aligned.m8n8.x4.trans.shared.b16 {%0,%1,%2,%3}, [%4];"
                 : "=r"(r[0]), "=r"(r[1]), "=r"(r[2]), "=r"(r[3]) : "r"(addr));
}

__global__ __launch_bounds__(256, 2)
void k_gemm_tc(int useH, int K,
               const float* __restrict__ att_s, const float* __restrict__ att_d) {
    const __nv_bfloat16* Ah = useH ? g_hh : g_xh;
    const __nv_bfloat16* Al = useH ? g_hl : g_xl;
    const __nv_bfloat16* Wh = useH ? g_w2h : g_w1h;
    const __nv_bfloat16* Wl = useH ? g_w2l : g_w1l;
    __shared__ __nv_bfloat16 AsH[128][40];
    __shared__ __nv_bfloat16 AsL[128][40];
    __shared__ __nv_bfloat16 BsH[32][136];
    __shared__ __nv_bfloat16 BsL[32][136];
    int tid = threadIdx.x;
    int lid = tid & 31, wid = tid >> 5;
    int wr = wid >> 1, wc = wid & 1;
    int lrow = lid & 7, seg = lid >> 3;

    const __nv_bfloat16* Abh = Ah + (size_t)blockIdx.x * 128 * K;
    const __nv_bfloat16* Abl = Al + (size_t)blockIdx.x * 128 * K;
    int bn0 = blockIdx.y * 128;

    float c[2][8][4];
#pragma unroll
    for (int mt = 0; mt < 2; mt++)
#pragma unroll
        for (int nt = 0; nt < 8; nt++)
#pragma unroll
            for (int q = 0; q < 4; q++) c[mt][nt][q] = 0.f;

    for (int k0 = 0; k0 < K; k0 += 32) {
#pragma unroll
        for (int i = 0; i < 2; i++) {
            int id = tid + 256 * i;
            int row = id >> 2, sq = id & 3;
            uint4 vh = *(const uint4*)(Abh + (size_t)row * K + k0 + sq * 8);
            uint4 vl = *(const uint4*)(Abl + (size_t)row * K + k0 + sq * 8);
            *(uint4*)&AsH[row][sq * 8] = vh;
            *(uint4*)&AsL[row][sq * 8] = vl;
        }
#pragma unroll
        for (int i = 0; i < 2; i++) {
            int id = tid + 256 * i;
            int kr = id >> 4, nq = id & 15;
            uint4 vh = *(const uint4*)(Wh + (size_t)(k0 + kr) * HC_ + bn0 + nq * 8);
            uint4 vl = *(const uint4*)(Wl + (size_t)(k0 + kr) * HC_ + bn0 + nq * 8);
            *(uint4*)&BsH[kr][nq * 8] = vh;
            *(uint4*)&BsL[kr][nq * 8] = vl;
        }
        __syncthreads();

#pragma unroll
        for (int ks = 0; ks < 2; ks++) {
            int kc = ks * 16;
            unsigned aH[2][4], aL[2][4];
            int ar = (seg & 1) * 8 + lrow;
            int ac = kc + (seg >> 1) * 8;
#pragma unroll
            for (int mt = 0; mt < 2; mt++) {
                int m = wr * 32 + mt * 16 + ar;
                ldsm4(aH[mt], sptr(&AsH[m][ac]));
                ldsm4(aL[mt], sptr(&AsL[m][ac]));
            }
            int br = kc + (seg & 1) * 8 + lrow;
            int bcoff = (seg >> 1) * 8;
#pragma unroll
            for (int ntp = 0; ntp < 4; ntp++) {
                int n0 = wc * 64 + ntp * 16 + bcoff;
                unsigned bH[4], bL[4];
                ldsm4t(bH, sptr(&BsH[br][n0]));
                ldsm4t(bL, sptr(&BsL[br][n0]));
#pragma unroll
                for (int half = 0; half < 2; half++) {
                    int nt = 2 * ntp + half;
                    unsigned b0H = bH[2 * half], b1H = bH[2 * half + 1];
                    unsigned b0L = bL[2 * half], b1L = bL[2 * half + 1];
#pragma unroll
                    for (int mt = 0; mt < 2; mt++) {
                        mma16(c[mt][nt], aH[mt], b0H, b1H);
                        mma16(c[mt][nt], aL[mt], b0H, b1H);
                        mma16(c[mt][nt], aH[mt], b0L, b1L);
                    }
                }
            }
        }
        __syncthreads();
    }

    int g4 = lid >> 2, t4 = lid & 3;

#pragma unroll
    for (int mt = 0; mt < 2; mt++) {
#pragma unroll
        for (int nt = 0; nt < 8; nt++) {
            int row = blockIdx.x * 128 + wr * 32 + mt * 16 + g4;
            int col = bn0 + wc * 64 + nt * 8 + 2 * t4;
            *(__half2*)(g_xwh + (size_t)row * HC_ + col) =
                __floats2half2_rn(c[mt][nt][0], c[mt][nt][1]);
            *(__half2*)(g_xwh + (size_t)(row + 8) * HC_ + col) =
                __floats2half2_rn(c[mt][nt][2], c[mt][nt][3]);
        }
    }

    int head = blockIdx.y * 2 + wc;
    const float* Asv = att_s + head * 64;
    const float* Adv = att_d + head * 64;
#pragma unroll
    for (int mt = 0; mt < 2; mt++) {
        float s0 = 0.f, s1 = 0.f, d0 = 0.f, d1 = 0.f;
#pragma unroll
        for (int nt = 0; nt < 8; nt++) {
            int cb = nt * 8 + 2 * t4;
            float a0 = Asv[cb], a1 = Asv[cb + 1];
            float b0 = Adv[cb], b1 = Adv[cb + 1];
            s0 += c[mt][nt][0] * a0 + c[mt][nt][1] * a1;
            s1 += c[mt][nt][2] * a0 + c[mt][nt][3] * a1;
            d0 += c[mt][nt][0] * b0 + c[mt][nt][1] * b1;
            d1 += c[mt][nt][2] * b0 + c[mt][nt][3] * b1;
        }
#pragma unroll
        for (int off = 1; off <= 2; off <<= 1) {
            s0 += __shfl_xor_sync(0xffffffffu, s0, off);
            s1 += __shfl_xor_sync(0xffffffffu, s1, off);
            d0 += __shfl_xor_sync(0xffffffffu, d0, off);
            d1 += __shfl_xor_sync(0xffffffffu, d1, off);
        }
        if (t4 == 0) {
            int r = blockIdx.x * 128 + wr * 32 + mt * 16 + g4;
            g_asrc[r * 4 + head]       = s0;
            g_adst[r * 4 + head]       = d0;
            g_asrc[(r + 8) * 4 + head] = s1;
            g_adst[(r + 8) * 4 + head] = d1;
        }
    }
}

// ---------------- GAT aggregation (warp per node, fp16 gather, prefetch) ------
__global__ void k_agg(const float* __restrict__ bias,
                      const float* __restrict__ poolw,
                      const float* __restrict__ poolb,
                      int writeH, int seg) {
    int n = (blockIdx.x * blockDim.x + threadIdx.x) >> 5;
    int lane = threadIdx.x & 31;
    if (n >= NT_) return;
    int h = lane >> 3;

    float4 d4 = *(const float4*)(g_adst + n * 4);
    float4 s4 = *(const float4*)(g_asrc + n * 4);
    float adh = (h == 0) ? d4.x : (h == 1) ? d4.y : (h == 2) ? d4.z : d4.w;
    float ash = (h == 0) ? s4.x : (h == 1) ? s4.y : (h == 2) ? s4.z : s4.w;

    int r0 = g_row[n], r1 = g_row[n + 1];

    float wself = __expf(lrelu(ash + adh));
    float den = wself;
    uint4 qs = *(const uint4*)(g_xwh + (size_t)n * HC_ + lane * 8);
    float2 s0 = __half22float2(*(__half2*)&qs.x);
    float2 s1 = __half22float2(*(__half2*)&qs.y);
    float2 s2 = __half22float2(*(__half2*)&qs.z);
    float2 s3 = __half22float2(*(__half2*)&qs.w);
    float4 acc0 = {wself*s0.x, wself*s0.y, wself*s1.x, wself*s1.y};
    float4 acc1 = {wself*s2.x, wself*s2.y, wself*s3.x, wself*s3.y};

    int sN = 0; float asN = 0.f;
    if (r0 < r1) { sN = g_csr[r0]; asN = g_asrc[sN * 4 + h]; }
    for (int e = r0; e < r1; e++) {
        int s = sN; float as = asN;
        int eN = (e + 1 < r1) ? e + 1 : e;
        sN = g_csr[eN];
        asN = g_asrc[sN * 4 + h];
        float wgt = __expf(lrelu(as + adh));
        den += wgt;
        uint4 q = *(const uint4*)(g_xwh + (size_t)s * HC_ + lane * 8);
        float2 f0 = __half22float2(*(__half2*)&q.x);
        float2 f1 = __half22float2(*(__half2*)&q.y);
        float2 f2 = __half22float2(*(__half2*)&q.z);
        float2 f3 = __half22float2(*(__half2*)&q.w);
        acc0.x += wgt * f0.x; acc0.y += wgt * f0.y;
        acc0.z += wgt * f1.x; acc0.w += wgt * f1.y;
        acc1.x += wgt * f2.x; acc1.y += wgt * f2.y;
        acc1.z += wgt * f3.x; acc1.w += wgt * f3.y;
    }
    float rden = 1.f / (den + 1e-16f);
    acc0.x *= rden; acc0.y *= rden; acc0.z *= rden; acc0.w *= rden;
    acc1.x *= rden; acc1.y *= rden; acc1.z *= rden; acc1.w *= rden;

    const float* bp = bias + lane * 8;
    float v[8];
    v[0] = elu1(acc0.x + bp[0]); v[1] = elu1(acc0.y + bp[1]);
    v[2] = elu1(acc0.z + bp[2]); v[3] = elu1(acc0.w + bp[3]);
    v[4] = elu1(acc1.x + bp[4]); v[5] = elu1(acc1.y + bp[5]);
    v[6] = elu1(acc1.z + bp[6]); v[7] = elu1(acc1.w + bp[7]);

    if (writeH) {
        __nv_bfloat162 hh[4], hl[4];
#pragma unroll
        for (int j = 0; j < 4; j++) {
            __nv_bfloat162 hi = __floats2bfloat162_rn(v[2*j], v[2*j+1]);
            __nv_bfloat162 lo = __floats2bfloat162_rn(
                v[2*j]   - __bfloat162float(hi.x),
                v[2*j+1] - __bfloat162float(hi.y));
            hh[j] = hi; hl[j] = lo;
        }
        *(uint4*)(g_hh + (size_t)n * HC_ + lane * 8) = *(uint4*)hh;
        *(uint4*)(g_hl + (size_t)n * HC_ + lane * 8) = *(uint4*)hl;
    }

    const float* pw = poolw + lane * 8;
    float p = v[0]*pw[0] + v[1]*pw[1] + v[2]*pw[2] + v[3]*pw[3]
            + v[4]*pw[4] + v[5]*pw[5] + v[6]*pw[6] + v[7]*pw[7];
#pragma unroll
    for (int off = 16; off >= 1; off >>= 1)
        p += __shfl_xor_sync(0xffffffffu, p, off);
    if (lane == 0)
        g_feat[(n >> 11) * (3 * N_) + seg * N_ + (n & 2047)] = p + poolb[0];
}

// ---------------- LayerNorm in place (48 rows) --------------------------------
__global__ void k_ln(const float* __restrict__ w, const float* __restrict__ b) {
    __shared__ float red[8];
    __shared__ float tot;
    int row = blockIdx.x;
    float* p = g_feat + (row / 3) * (3 * N_) + (row % 3) * N_;
    int t = threadIdx.x;
    float v[8];
    float s = 0.f;
#pragma unroll
    for (int i = 0; i < 8; i++) { v[i] = p[t + 256 * i]; s += v[i]; }
#pragma unroll
    for (int off = 16; off >= 1; off >>= 1) s += __shfl_xor_sync(0xffffffffu, s, off);
    if ((t & 31) == 0) red[t >> 5] = s;
    __syncthreads();
    if (t == 0) { float z = 0.f; for (int i = 0; i < 8; i++) z += red[i]; tot = z; }
    __syncthreads();
    float mu = tot * (1.f / 2048.f);
    float q = 0.f;
#pragma unroll
    for (int i = 0; i < 8; i++) { float d = v[i] - mu; q += d * d; }
#pragma unroll
    for (int off = 16; off >= 1; off >>= 1) q += __shfl_xor_sync(0xffffffffu, q, off);
    __syncthreads();
    if ((t & 31) == 0) red[t >> 5] = q;
    __syncthreads();
    if (t == 0) { float z = 0.f; for (int i = 0; i < 8; i++) z += red[i]; tot = z; }
    __syncthreads();
    float r = rsqrtf(tot * (1.f / 2048.f) + 1e-5f);
#pragma unroll
    for (int i = 0; i < 8; i++) {
        int idx = t + 256 * i;
        p[idx] = (v[i] - mu) * r * w[idx] + b[idx];
    }
}

// ---------------- fc0 partial GEMM (24 k-splits, 256 threads) ------------------
__global__ __launch_bounds__(256)
void k_fc0(const float* __restrict__ W) {
    __shared__ float sa[16][128];
    int tid = threadIdx.x;                 // 256
    int jt = tid & 127;                    // j within tile
    int half = tid >> 7;                   // 0: batch 0-7, 1: batch 8-15
    int j = blockIdx.x * 128 + jt;
    int k0 = blockIdx.y * 256;
    float acc[8];
#pragma unroll
    for (int bi = 0; bi < 8; bi++) acc[bi] = 0.f;
    for (int kt = k0; kt < k0 + 256; kt += 128) {
        // load A slab 16x128 cooperatively (2048 elems / 256 thr = 8 each)
#pragma unroll
        for (int i = 0; i < 8; i++) {
            int id = tid + 256 * i;
            sa[id >> 7][id & 127] = g_feat[(id >> 7) * (3 * N_) + kt + (id & 127)];
        }
        __syncthreads();
#pragma unroll 8
        for (int kk = 0; kk < 128; kk++) {
            float wv = W[(size_t)(kt + kk) * FC0_ + j];
#pragma unroll
            for (int bi = 0; bi < 8; bi++)
                acc[bi] += sa[half * 8 + bi][kk] * wv;
        }
        __syncthreads();
    }
#pragma unroll
    for (int bi = 0; bi < 8; bi++)
        g_part[((size_t)blockIdx.y * 16 + half * 8 + bi) * FC0_ + j] = acc[bi];
}

// ---------------- fused FC tail ------------------------------------------------
__global__ __launch_bounds__(512)
void k_fctail(const float* __restrict__ e0b,
              const float* __restrict__ e1w, const float* __restrict__ e1b,
              const float* __restrict__ e2w, const float* __restrict__ e2b,
              const float* __restrict__ lw,  const float* __restrict__ lb,
              float* __restrict__ out, int out_n) {
    __shared__ float se0[FC0_];
    __shared__ float se1[FC1_];
    __shared__ float se2[OMIC_];
    int b = blockIdx.x;
    int t = threadIdx.x;

    for (int j = t; j < FC0_; j += 512) {
        float s = 0.f;
#pragma unroll
        for (int p = 0; p < NSPLIT_; p++)
            s += g_part[((size_t)p * 16 + b) * FC0_ + j];
        se0[j] = elu1(s + e0b[j]);
    }
    __syncthreads();

    {
        float s = 0.f;
        for (int k = 0; k < FC0_; k++)
            s += se0[k] * e1w[(size_t)k * FC1_ + t];
        se1[t] = elu1(s + e1b[t]);
    }
    __syncthreads();

    if (t < OMIC_) {
        float s = 0.f;
        for (int k = 0; k < FC1_; k++)
            s += se1[k] * e2w[(size_t)k * OMIC_ + t];
        se2[t] = elu1(s + e2b[t]);
    }
    __syncthreads();

    if (t < OUT_) {
        float a = 0.f;
        for (int k = 0; k < OMIC_; k++) a += se2[k] * lw[k * OUT_ + t];
        int oi = b * OUT_ + t;
        if (oi < out_n) out[oi] = a + lb[t];
    }
}

// ---------------- driver ----------------------------------------------------------
extern "C" void kernel_launch(void* const* d_in, const int* in_sizes, int n_in,
                              void* d_out, int out_size) {
    const float* x   = (const float*)d_in[0];
    const void*  ei  = d_in[1];
    const float* w1  = (const float*)d_in[2];
    const float* as1 = (const float*)d_in[3];
    const float* ad1 = (const float*)d_in[4];
    const float* b1  = (const float*)d_in[5];
    const float* p1w = (const float*)d_in[6];
    const float* p1b = (const float*)d_in[7];
    const float* w2  = (const float*)d_in[8];
    const float* as2 = (const float*)d_in[9];
    const float* ad2 = (const float*)d_in[10];
    const float* b2  = (const float*)d_in[11];
    const float* p2w = (const float*)d_in[12];
    const float* p2b = (const float*)d_in[13];
    const float* lnw = (const float*)d_in[14];
    const float* lnb = (const float*)d_in[15];
    const float* e0w = (const float*)d_in[16];
    const float* e0b = (const float*)d_in[17];
    const float* e1w = (const float*)d_in[18];
    const float* e1b = (const float*)d_in[19];
    const float* e2w = (const float*)d_in[20];
    const float* e2b = (const float*)d_in[21];
    const float* lw  = (const float*)d_in[22];
    const float* lb  = (const float*)d_in[23];
    float* out = (float*)d_out;

    k_zero<<<4096, 256>>>(ei, x, w1, w2);                              // 1
    k_deg<<<E_ / 256, 256>>>(ei);                                      // 2
    k_scan1<<<128, 256>>>();                                           // 3
    k_gemm_tc<<<dim3(NT_ / 128, 2), 256>>>(0, INCH_, as1, ad1);        // 4 <- profiled
    k_scan3b<<<128, 256>>>();                                          // 5
    k_scatter<<<E_ / 256, 256>>>(ei);                                  // 6
    k_sortseg<<<NT_ / 256, 256>>>();                                   // 7
    k_agg<<<NT_ / 8, 256>>>(b1, p1w, p1b, 1, 1);                       // 8
    k_gemm_tc<<<dim3(NT_ / 128, 2), 256>>>(1, HC_, as2, ad2);          // 9
    k_agg<<<NT_ / 8, 256>>>(b2, p2w, p2b, 0, 2);                       // 10
    k_ln<<<48, 256>>>(lnw, lnb);                                       // 11
    k_fc0<<<dim3(FC0_ / 128, NSPLIT_), 256>>>(e0w);                    // 12
    k_fctail<<<B_, 512>>>(e0b, e1w, e1b, e2w, e2b, lw, lb, out, out_size); // 13
}